// round 3
// baseline (speedup 1.0000x reference)
#include <cuda_runtime.h>
#include <math.h>
#include <stdint.h>

#define NB 16
#define NN 2048
#define NTOT (NB*NN)          // 32768
#define KNB 16
#define IND 128
#define OUTD 256
#define NEDGE (NTOT*KNB)      // 524288

// ---------------- scratch (device globals; no allocations allowed) ----------
__device__ float d_sqn[NTOT];
__device__ int   d_nbr[NTOT*KNB];
__device__ float d_g1[(size_t)NTOT*OUTD];
__device__ float d_h1[(size_t)NTOT*OUTD];
__device__ float d_g2[(size_t)NTOT*OUTD];
__device__ float d_sc[(size_t)NTOT*OUTD];

// ---------------- f32x2 helpers ----------------
__device__ __forceinline__ unsigned long long pack_dup(float v) {
    unsigned long long r;
    asm("mov.b64 %0, {%1, %1};" : "=l"(r) : "f"(v));
    return r;
}
__device__ __forceinline__ unsigned long long fma2(unsigned long long a,
                                                   unsigned long long b,
                                                   unsigned long long c) {
    unsigned long long d;
    asm("fma.rn.f32x2 %0, %1, %2, %3;" : "=l"(d) : "l"(a), "l"(b), "l"(c));
    return d;
}
__device__ __forceinline__ void unpack2(unsigned long long v, float& lo, float& hi) {
    asm("mov.b64 {%0, %1}, %2;" : "=f"(lo), "=f"(hi) : "l"(v));
}

// ---------------- squared norms ----------------
__global__ void k_sqn(const float* __restrict__ x) {
    int i = blockIdx.x * blockDim.x + threadIdx.x;
    if (i >= NTOT) return;
    const float4* p = (const float4*)(x + (size_t)i * IND);
    float s = 0.f;
#pragma unroll
    for (int j = 0; j < IND/4; j++) {
        float4 v = p[j];
        s = fmaf(v.x, v.x, s); s = fmaf(v.y, v.y, s);
        s = fmaf(v.z, v.z, s); s = fmaf(v.w, v.w, s);
    }
    d_sqn[i] = s;
}

// ---------------- kNN: per-graph all-pairs + top-16 (f32x2 compute) --------
// grid (NN/128, NB), block 256. Tile: 128 queries x 128 candidates resident.
#define QT 128
#define CT 128
#define QP 132          // smem pitch for [d][node] tiles
#define DP 130          // dist pitch (even -> 8B-aligned pair stores)

__global__ __launch_bounds__(256) void k_knn(const float* __restrict__ x,
                                             float* __restrict__ esrc,
                                             float* __restrict__ edst,
                                             int write_edges) {
    extern __shared__ float sm[];
    float* qs   = sm;                  // [IND][QP]  (transposed: [d][q])
    float* cs   = qs + IND*QP;         // [IND][QP]  ([d][c])
    float* dist = cs + IND*QP;         // [QT][DP]
    float* csq  = dist + QT*DP;        // [CT]

    const int b  = blockIdx.y;
    const int qb = blockIdx.x * QT;
    const int t  = threadIdx.x;
    const int tx = t & 15, ty = t >> 4;
    const float* xb = x + (size_t)b * NN * IND;
    const float FINF = __int_as_float(0x7f800000);

    // load query tile transposed [d][q]
    for (int idx = t; idx < QT * (IND/4); idx += 256) {
        int q = idx & (QT - 1);
        int dc = idx >> 7;                       // 0..31
        float4 v = *(const float4*)(xb + (size_t)(qb + q) * IND + dc * 4);
        qs[(dc*4 + 0)*QP + q] = v.x;
        qs[(dc*4 + 1)*QP + q] = v.y;
        qs[(dc*4 + 2)*QP + q] = v.z;
        qs[(dc*4 + 3)*QP + q] = v.w;
    }

    // selection state: 2 threads per query (halves of candidate tile)
    const int myq   = t >> 1;          // 0..127
    const int myh   = t & 1;           // half
    float bd[KNB]; int bi[KNB];
#pragma unroll
    for (int k = 0; k < KNB; k++) { bd[k] = FINF; bi[k] = 0; }

    for (int cb = 0; cb < NN; cb += CT) {
        // load candidate tile transposed [d][c]
        for (int idx = t; idx < CT * (IND/4); idx += 256) {
            int c = idx & (CT - 1);
            int dc = idx >> 7;
            float4 v = *(const float4*)(xb + (size_t)(cb + c) * IND + dc * 4);
            cs[(dc*4 + 0)*QP + c] = v.x;
            cs[(dc*4 + 1)*QP + c] = v.y;
            cs[(dc*4 + 2)*QP + c] = v.z;
            cs[(dc*4 + 3)*QP + c] = v.w;
        }
        if (t < CT) csq[t] = d_sqn[b * NN + cb + t];
        __syncthreads();

        // 128x128 dots; per-thread 8q x 8c split into 2x 4-wide groups.
        // queries: ty*4+u (u<4), 64+ty*4+(u-4); cands: tx*4+(0..3), 64+tx*4+(0..3)
        unsigned long long acc[8][4];
#pragma unroll
        for (int u = 0; u < 8; u++)
#pragma unroll
            for (int v = 0; v < 4; v++) acc[u][v] = 0ULL;

#pragma unroll 8
        for (int d = 0; d < IND; d++) {
            const float* qr = qs + d * QP + ty * 4;
            const float* cr = cs + d * QP + tx * 4;
            float4 q0 = *(const float4*)qr;
            float4 q1 = *(const float4*)(qr + 64);
            unsigned long long c0 = *(const unsigned long long*)cr;
            unsigned long long c1 = *(const unsigned long long*)(cr + 2);
            unsigned long long c2 = *(const unsigned long long*)(cr + 64);
            unsigned long long c3 = *(const unsigned long long*)(cr + 66);
            unsigned long long qq[8];
            qq[0] = pack_dup(q0.x); qq[1] = pack_dup(q0.y);
            qq[2] = pack_dup(q0.z); qq[3] = pack_dup(q0.w);
            qq[4] = pack_dup(q1.x); qq[5] = pack_dup(q1.y);
            qq[6] = pack_dup(q1.z); qq[7] = pack_dup(q1.w);
#pragma unroll
            for (int u = 0; u < 8; u++) {
                acc[u][0] = fma2(qq[u], c0, acc[u][0]);
                acc[u][1] = fma2(qq[u], c1, acc[u][1]);
                acc[u][2] = fma2(qq[u], c2, acc[u][2]);
                acc[u][3] = fma2(qq[u], c3, acc[u][3]);
            }
        }

        // keys into dist: key = csq[c] - 2*dot; self -> +inf
#pragma unroll
        for (int u = 0; u < 8; u++) {
            int ql = (u < 4) ? (ty*4 + u) : (64 + ty*4 + u - 4);
#pragma unroll
            for (int v = 0; v < 4; v++) {
                int c0i = (v < 2) ? (tx*4 + 2*v) : (64 + tx*4 + 2*(v - 2));
                float dlo, dhi;
                unpack2(acc[u][v], dlo, dhi);
                float k0 = fmaf(-2.f, dlo, csq[c0i]);
                float k1 = fmaf(-2.f, dhi, csq[c0i + 1]);
                if (qb + ql == cb + c0i)     k0 = FINF;
                if (qb + ql == cb + c0i + 1) k1 = FINF;
                float2 kv = make_float2(k0, k1);
                *(float2*)(dist + ql * DP + c0i) = kv;
            }
        }
        __syncthreads();

        // selection: thread scans its 64-cand half, ascending index order.
        {
            const float* dr = dist + myq * DP + myh * 64;
            const int ibase = cb + myh * 64;
#pragma unroll 4
            for (int ci = 0; ci < 64; ci++) {
                float key = dr[ci];
                if (key < bd[KNB - 1]) {
                    bd[KNB - 1] = key; bi[KNB - 1] = ibase + ci;
#pragma unroll
                    for (int j = KNB - 1; j > 0; j--) {
                        if (bd[j] < bd[j - 1]) {
                            float tf = bd[j]; bd[j] = bd[j - 1]; bd[j - 1] = tf;
                            int   ti = bi[j]; bi[j] = bi[j - 1]; bi[j - 1] = ti;
                        }
                    }
                }
            }
        }
        __syncthreads();
    }

    // dump both half-lists to smem (reuse dist): keys at [q][h*16+j], idx at [q][32+h*16+j]
#pragma unroll
    for (int j = 0; j < KNB; j++) {
        dist[myq * DP + myh * KNB + j] = bd[j];
        dist[myq * DP + 32 + myh * KNB + j] = __int_as_float(bi[j]);
    }
    __syncthreads();

    // one thread per query merges the two sorted lists (tie: lower idx first)
    if (t < QT) {
        const float* ka = dist + t * DP;
        const float* kb_ = ka + KNB;
        const float* ia = ka + 32;
        const float* ib = ka + 48;
        int pa = 0, pb = 0;
        int qg = b * NN + qb + t;
#pragma unroll
        for (int k = 0; k < KNB; k++) {
            float kva = ka[pa], kvb = kb_[pb];
            int   iva = __float_as_int(ia[pa]), ivb = __float_as_int(ib[pb]);
            bool takeA = (kva < kvb) || (kva == kvb && iva < ivb);
            int sel = takeA ? iva : ivb;
            if (takeA) pa++; else pb++;
            int sg = b * NN + sel;
            size_t e = (size_t)qg * KNB + k;
            d_nbr[e] = sg;
            if (write_edges) {
                esrc[e] = (float)sg;
                edst[e] = (float)qg;
            }
        }
    }
}

// ---------------- SGEMM 128x128, f32x2 micro, K chunk 32 ----------------
#define GKC 32
__global__ __launch_bounds__(256) void k_gemm(const float* __restrict__ A,
                                              const float* __restrict__ B,
                                              const float* __restrict__ bias,
                                              float* __restrict__ C,
                                              int Kd, int Nc, int addBias) {
    __shared__ float As[GKC][QP];   // [k][m]
    __shared__ float Bs[GKC][QP];   // [k][n]
    const int t = threadIdx.x;
    const int tx = t & 15, ty = t >> 4;
    const int nb = blockIdx.x * 128, mb = blockIdx.y * 128;

    unsigned long long acc[8][4];
#pragma unroll
    for (int u = 0; u < 8; u++)
#pragma unroll
        for (int v = 0; v < 4; v++) acc[u][v] = 0ULL;

    for (int kb = 0; kb < Kd; kb += GKC) {
        // A chunk transposed: 128 rows x 32 cols
        for (int idx = t; idx < 128 * (GKC/4); idx += 256) {
            int m = idx & 127, kc = idx >> 7;    // kc 0..7
            float4 v = *(const float4*)(A + (size_t)(mb + m) * Kd + kb + kc * 4);
            As[kc*4 + 0][m] = v.x; As[kc*4 + 1][m] = v.y;
            As[kc*4 + 2][m] = v.z; As[kc*4 + 3][m] = v.w;
        }
        // B chunk natural [k][n]
        for (int idx = t; idx < GKC * (128/4); idx += 256) {
            int n4 = idx & 31, k = idx >> 5;
            float4 v = *(const float4*)(B + (size_t)(kb + k) * Nc + nb + n4 * 4);
            *(float4*)(&Bs[k][n4 * 4]) = v;
        }
        __syncthreads();

#pragma unroll
        for (int k = 0; k < GKC; k++) {
            const float* ar = &As[k][ty * 4];
            const float* br = &Bs[k][tx * 4];
            float4 a0 = *(const float4*)ar;
            float4 a1 = *(const float4*)(ar + 64);
            unsigned long long b0 = *(const unsigned long long*)br;
            unsigned long long b1 = *(const unsigned long long*)(br + 2);
            unsigned long long b2 = *(const unsigned long long*)(br + 64);
            unsigned long long b3 = *(const unsigned long long*)(br + 66);
            unsigned long long aa[8];
            aa[0] = pack_dup(a0.x); aa[1] = pack_dup(a0.y);
            aa[2] = pack_dup(a0.z); aa[3] = pack_dup(a0.w);
            aa[4] = pack_dup(a1.x); aa[5] = pack_dup(a1.y);
            aa[6] = pack_dup(a1.z); aa[7] = pack_dup(a1.w);
#pragma unroll
            for (int u = 0; u < 8; u++) {
                acc[u][0] = fma2(aa[u], b0, acc[u][0]);
                acc[u][1] = fma2(aa[u], b1, acc[u][1]);
                acc[u][2] = fma2(aa[u], b2, acc[u][2]);
                acc[u][3] = fma2(aa[u], b3, acc[u][3]);
            }
        }
        __syncthreads();
    }

#pragma unroll
    for (int u = 0; u < 8; u++) {
        int m = mb + ((u < 4) ? (ty*4 + u) : (64 + ty*4 + u - 4));
#pragma unroll
        for (int g = 0; g < 2; g++) {
            int n = nb + ((g == 0) ? (tx*4) : (64 + tx*4));
            float4 o;
            unpack2(acc[u][g*2 + 0], o.x, o.y);
            unpack2(acc[u][g*2 + 1], o.z, o.w);
            if (addBias) {
                o.x += bias[n + 0]; o.y += bias[n + 1];
                o.z += bias[n + 2]; o.w += bias[n + 3];
            }
            *(float4*)(C + (size_t)m * Nc + n) = o;
        }
    }
}

// ---------------- GCN aggregation (deg == 17 exactly for all nodes) ---------
__global__ __launch_bounds__(256) void k_agg_relu(const float* __restrict__ g,
                                                  const float* __restrict__ bias,
                                                  float* __restrict__ out) {
    const int node = blockIdx.x;
    const int t = threadIdx.x;
    __shared__ int nb_s[KNB];
    if (t < KNB) nb_s[t] = d_nbr[(size_t)node * KNB + t];
    __syncthreads();
    const float dinv = rsqrtf(17.0f);
    const float norm = dinv * dinv;
    float acc = 0.f;
#pragma unroll
    for (int k = 0; k < KNB; k++)
        acc += g[(size_t)nb_s[k] * OUTD + t] * norm;
    acc += g[(size_t)node * OUTD + t] * (1.0f / 17.0f);
    acc += bias[t];
    out[(size_t)node * OUTD + t] = fmaxf(acc, 0.f);
}

__global__ __launch_bounds__(256) void k_agg_final(const float* __restrict__ g,
                                                   const float* __restrict__ bias,
                                                   const float* __restrict__ sc,
                                                   float* __restrict__ out) {
    const int node = blockIdx.x;
    const int t = threadIdx.x;
    __shared__ int nb_s[KNB];
    if (t < KNB) nb_s[t] = d_nbr[(size_t)node * KNB + t];
    __syncthreads();
    const float dinv = rsqrtf(17.0f);
    const float norm = dinv * dinv;
    float acc = 0.f;
#pragma unroll
    for (int k = 0; k < KNB; k++)
        acc += g[(size_t)nb_s[k] * OUTD + t] * norm;
    acc += g[(size_t)node * OUTD + t] * (1.0f / 17.0f);
    acc += bias[t];
    acc += sc[(size_t)node * OUTD + t];
    out[(size_t)node * OUTD + t] = acc;
}

// ---------------- launch ----------------
extern "C" void kernel_launch(void* const* d_in, const int* in_sizes, int n_in,
                              void* d_out, int out_size) {
    const float* x  = (const float*)d_in[0];
    const float* W1 = (const float*)d_in[2];
    const float* b1 = (const float*)d_in[3];
    const float* W2 = (const float*)d_in[4];
    const float* b2 = (const float*)d_in[5];
    const float* Ws = (const float*)d_in[6];
    const float* bs = (const float*)d_in[7];

    float* out  = (float*)d_out;
    float* esrc = out + (size_t)NTOT * OUTD;
    float* edst = esrc + NEDGE;
    int write_edges = (out_size >= (int)((size_t)NTOT * OUTD + 2 * NEDGE)) ? 1 : 0;

    float *g1, *h1, *g2, *sc;
    cudaGetSymbolAddress((void**)&g1, d_g1);
    cudaGetSymbolAddress((void**)&h1, d_h1);
    cudaGetSymbolAddress((void**)&g2, d_g2);
    cudaGetSymbolAddress((void**)&sc, d_sc);

    const int knn_smem = (IND*QP + IND*QP + QT*DP + CT) * (int)sizeof(float);
    static int attr_set = 0;
    cudaFuncSetAttribute(k_knn, cudaFuncAttributeMaxDynamicSharedMemorySize, knn_smem);
    (void)attr_set;

    // 1. squared norms
    k_sqn<<<(NTOT + 255) / 256, 256>>>(x);

    // 2. kNN + edge_index output
    k_knn<<<dim3(NN / QT, NB), 256, knn_smem>>>(x, esrc, edst, write_edges);

    // 3. g1 = x @ W1
    k_gemm<<<dim3(OUTD / 128, NTOT / 128), 256>>>(x, W1, b1, g1, IND, OUTD, 0);

    // 4. h1 = relu(agg(g1) + b1)
    k_agg_relu<<<NTOT, 256>>>(g1, b1, h1);

    // 5. g2 = h1 @ W2
    k_gemm<<<dim3(OUTD / 128, NTOT / 128), 256>>>(h1, W2, b2, g2, OUTD, OUTD, 0);

    // 6. sc = x @ Ws + bs
    k_gemm<<<dim3(OUTD / 128, NTOT / 128), 256>>>(x, Ws, bs, sc, IND, OUTD, 1);

    // 7. out = agg(g2) + b2 + sc
    k_agg_final<<<NTOT, 256>>>(g2, b2, sc, out);
}

// round 6
// speedup vs baseline: 1.2265x; 1.2265x over previous
#include <cuda_runtime.h>
#include <cuda_bf16.h>
#include <stdint.h>

#define NB 16
#define NN 2048
#define NTOT (NB*NN)
#define KNB 16
#define IND 128
#define OUTD 256
#define NEDGE (NTOT*KNB)

// ---------------- scratch ----------------
__device__ float d_sqn[NTOT];
__device__ int   d_nbr[NTOT*KNB];
__device__ float d_g1[(size_t)NTOT*OUTD];
__device__ float d_g2[(size_t)NTOT*OUTD];
__device__ float d_sc[(size_t)NTOT*OUTD];
__device__ __nv_bfloat16 d_xhi[(size_t)NTOT*IND];
__device__ __nv_bfloat16 d_xmd[(size_t)NTOT*IND];
__device__ __nv_bfloat16 d_xlo[(size_t)NTOT*IND];
__device__ __nv_bfloat16 d_h1hi[(size_t)NTOT*OUTD];
__device__ __nv_bfloat16 d_h1lo[(size_t)NTOT*OUTD];
__device__ __nv_bfloat16 d_w1hi[IND*OUTD],  d_w1lo[IND*OUTD];
__device__ __nv_bfloat16 d_w2hi[OUTD*OUTD], d_w2lo[OUTD*OUTD];
__device__ __nv_bfloat16 d_wshi[IND*OUTD],  d_wslo[IND*OUTD];

// ---------------- helpers ----------------
__device__ __forceinline__ uint32_t smem_u32(const void* p) {
    uint32_t a;
    asm("{ .reg .u64 t; cvta.to.shared.u64 t, %1; cvt.u32.u64 %0, t; }" : "=r"(a) : "l"(p));
    return a;
}
__device__ __forceinline__ void cpa16(uint32_t dst, const void* src) {
    asm volatile("cp.async.cg.shared.global [%0], [%1], 16;" :: "r"(dst), "l"(src));
}
__device__ __forceinline__ void cp_commit() { asm volatile("cp.async.commit_group;"); }
__device__ __forceinline__ void cp_wait0()  { asm volatile("cp.async.wait_group 0;"); }
__device__ __forceinline__ void ldsm4(uint32_t* r, uint32_t a) {
    asm volatile("ldmatrix.sync.aligned.m8n8.x4.shared.b16 {%0,%1,%2,%3}, [%4];"
        : "=r"(r[0]), "=r"(r[1]), "=r"(r[2]), "=r"(r[3]) : "r"(a));
}
__device__ __forceinline__ void ldsm2(uint32_t* r, uint32_t a) {
    asm volatile("ldmatrix.sync.aligned.m8n8.x2.shared.b16 {%0,%1}, [%2];"
        : "=r"(r[0]), "=r"(r[1]) : "r"(a));
}
__device__ __forceinline__ void ldsm2t(uint32_t* r, uint32_t a) {
    asm volatile("ldmatrix.sync.aligned.m8n8.x2.trans.shared.b16 {%0,%1}, [%2];"
        : "=r"(r[0]), "=r"(r[1]) : "r"(a));
}
__device__ __forceinline__ void mma16816(float* c, const uint32_t* a, const uint32_t* b) {
    asm volatile("mma.sync.aligned.m16n8k16.row.col.f32.bf16.bf16.f32 "
        "{%0,%1,%2,%3}, {%4,%5,%6,%7}, {%8,%9}, {%0,%1,%2,%3};"
        : "+f"(c[0]), "+f"(c[1]), "+f"(c[2]), "+f"(c[3])
        : "r"(a[0]), "r"(a[1]), "r"(a[2]), "r"(a[3]), "r"(b[0]), "r"(b[1]));
}

// ---------------- squared norms (fp32 exact) ----------------
__global__ void k_sqn(const float* __restrict__ x) {
    int i = blockIdx.x * blockDim.x + threadIdx.x;
    if (i >= NTOT) return;
    const float4* p = (const float4*)(x + (size_t)i * IND);
    float s = 0.f;
#pragma unroll
    for (int j = 0; j < IND/4; j++) {
        float4 v = p[j];
        s = fmaf(v.x, v.x, s); s = fmaf(v.y, v.y, s);
        s = fmaf(v.z, v.z, s); s = fmaf(v.w, v.w, s);
    }
    d_sqn[i] = s;
}

// ---------------- 3-way bf16 split of x ----------------
__global__ void k_split3(const float* __restrict__ x) {
    int i = blockIdx.x * blockDim.x + threadIdx.x;  // over NTOT*IND/4
    if (i >= NTOT * IND / 4) return;
    float4 v = ((const float4*)x)[i];
    float f[4] = {v.x, v.y, v.z, v.w};
    __nv_bfloat16 h[4], m[4], l[4];
#pragma unroll
    for (int j = 0; j < 4; j++) {
        h[j] = __float2bfloat16_rn(f[j]);
        float r1 = f[j] - __bfloat162float(h[j]);
        m[j] = __float2bfloat16_rn(r1);
        float r2 = r1 - __bfloat162float(m[j]);
        l[j] = __float2bfloat16_rn(r2);
    }
    ((uint2*)d_xhi)[i] = *(uint2*)h;
    ((uint2*)d_xmd)[i] = *(uint2*)m;
    ((uint2*)d_xlo)[i] = *(uint2*)l;
}

// ---------------- 2-way bf16 split (weights) ----------------
__global__ void k_splitw(const float* __restrict__ s, __nv_bfloat16* __restrict__ hi,
                         __nv_bfloat16* __restrict__ lo, int n) {
    int i = blockIdx.x * blockDim.x + threadIdx.x;
    if (i >= n) return;
    float f = s[i];
    __nv_bfloat16 h = __float2bfloat16_rn(f);
    hi[i] = h;
    lo[i] = __float2bfloat16_rn(f - __bfloat162float(h));
}

// ---------------- kNN via mma.sync bf16 (3-way split, 6 passes) -------------
#define PB 272                    // tile pitch bytes (136 bf16)
#define TQB (128*PB)              // 34816: 128-row tile
#define TCB (64*PB)               // 17408: 64-row tile
#define SQ 0
#define SC (3*TQB)                // candidate buffers: 2 x 3 x TCB
#define SCSQ (SC + 6*TCB)
#define SMTOT (SCSQ + 2*64*4)
#define NCH (NN/64)               // 32 chunks

__device__ __forceinline__ void ins16(float* bd, int* bi, float key, int idx) {
    if (key < bd[15]) {
        bd[15] = key; bi[15] = idx;
#pragma unroll
        for (int j = 15; j > 0; j--) {
            if (bd[j] < bd[j-1]) {
                float tf = bd[j]; bd[j] = bd[j-1]; bd[j-1] = tf;
                int   ti = bi[j]; bi[j] = bi[j-1]; bi[j-1] = ti;
            }
        }
    }
}

__global__ __launch_bounds__(256)
void k_knn(const __nv_bfloat16* __restrict__ xhi,
           const __nv_bfloat16* __restrict__ xmd,
           const __nv_bfloat16* __restrict__ xlo,
           float* __restrict__ esrc, float* __restrict__ edst, int we) {
    extern __shared__ char sm[];
    const uint32_t smb = smem_u32(sm);
    float* csq = (float*)(sm + SCSQ);
    const int t = threadIdx.x, w = t >> 5, lane = t & 31;
    const int b = blockIdx.y, qb = blockIdx.x * 128, gbase = b * NN;
    const float FINF = __int_as_float(0x7f800000);
    const __nv_bfloat16* xs[3] = {xhi, xmd, xlo};

    // prologue: 3 query tiles + candidate chunk 0 (3 splits)
    for (int s = 0; s < 3; s++) {
        for (int it = t; it < 2048; it += 256) {
            int row = it >> 4, c = it & 15;
            cpa16(smb + SQ + s*TQB + row*PB + c*16,
                  xs[s] + ((size_t)(gbase + qb + row) << 7) + c*8);
        }
        for (int it = t; it < 1024; it += 256) {
            int row = it >> 4, c = it & 15;
            cpa16(smb + SC + s*TCB + row*PB + c*16,
                  xs[s] + ((size_t)(gbase + row) << 7) + c*8);
        }
    }
    if (t < 64) csq[t] = d_sqn[gbase + t];
    cp_commit();

    // per-lane top-16 lists: list0 -> row r0, list1 -> row r0+8
    const int r0 = w * 16 + (lane >> 2);
    const int quarter = lane & 3;
    float bd0[16], bd1[16]; int bi0[16], bi1[16];
#pragma unroll
    for (int j = 0; j < 16; j++) { bd0[j] = FINF; bd1[j] = FINF; bi0[j] = 0; bi1[j] = 0; }

    for (int i = 0; i < NCH; i++) {
        cp_wait0();
        __syncthreads();
        const int buf = i & 1;
        if (i + 1 < NCH) {
            const int nb_ = (i + 1) & 1, cb2 = (i + 1) * 64;
            for (int s = 0; s < 3; s++)
                for (int it = t; it < 1024; it += 256) {
                    int row = it >> 4, c = it & 15;
                    cpa16(smb + SC + (nb_*3 + s)*TCB + row*PB + c*16,
                          xs[s] + ((size_t)(gbase + cb2 + row) << 7) + c*8);
                }
            if (t < 64) csq[nb_ * 64 + t] = d_sqn[gbase + cb2 + t];
            cp_commit();
        }
        const uint32_t chB = smb + SC + (buf*3) * TCB;
        const float* cs = csq + buf * 64;
        const int cb = i * 64;

        float acc[8][4];
#pragma unroll
        for (int nt = 0; nt < 8; nt++)
#pragma unroll
            for (int v = 0; v < 4; v++) acc[nt][v] = 0.f;

#pragma unroll 1
        for (int ks = 0; ks < 8; ks++) {
            uint32_t af[3][4];
            uint32_t abase = smb + SQ + (w*16 + (lane & 15))*PB + ks*32 + (lane >> 4)*16;
#pragma unroll
            for (int s = 0; s < 3; s++) ldsm4(af[s], abase + s*TQB);
#pragma unroll
            for (int nt = 0; nt < 8; nt++) {
                uint32_t bbase = chB + (nt*8 + (lane & 7))*PB + ks*32 + ((lane >> 3) & 1)*16;
                uint32_t bf[3][2];
#pragma unroll
                for (int s = 0; s < 3; s++) ldsm2(bf[s], bbase + s*TCB);
                mma16816(acc[nt], af[0], bf[0]);   // hh
                mma16816(acc[nt], af[0], bf[1]);   // hm
                mma16816(acc[nt], af[1], bf[0]);   // mh
                mma16816(acc[nt], af[0], bf[2]);   // hl
                mma16816(acc[nt], af[2], bf[0]);   // lh
                mma16816(acc[nt], af[1], bf[1]);   // mm
            }
        }
        // selection from fragments
#pragma unroll
        for (int nt = 0; nt < 8; nt++) {
            int cl = nt*8 + 2*quarter;
            float cq0 = cs[cl], cq1 = cs[cl + 1];
            float k00 = fmaf(-2.f, acc[nt][0], cq0);
            float k01 = fmaf(-2.f, acc[nt][1], cq1);
            float k10 = fmaf(-2.f, acc[nt][2], cq0);
            float k11 = fmaf(-2.f, acc[nt][3], cq1);
            int ci = cb + cl;
            if (qb + r0 == ci)         k00 = FINF;
            if (qb + r0 == ci + 1)     k01 = FINF;
            if (qb + r0 + 8 == ci)     k10 = FINF;
            if (qb + r0 + 8 == ci + 1) k11 = FINF;
            ins16(bd0, bi0, k00, ci);
            ins16(bd0, bi0, k01, ci + 1);
            ins16(bd1, bi1, k10, ci);
            ins16(bd1, bi1, k11, ci + 1);
        }
    }
    __syncthreads();

    // dump 4 lists/query (reuse candidate area)
    float* dk = (float*)(sm + SC);
    int*   di = (int*)(sm + SC + 32768);
#pragma unroll
    for (int j = 0; j < 16; j++) {
        dk[(r0*4 + quarter)*16 + j] = bd0[j];
        di[(r0*4 + quarter)*16 + j] = bi0[j];
        dk[((r0 + 8)*4 + quarter)*16 + j] = bd1[j];
        di[((r0 + 8)*4 + quarter)*16 + j] = bi1[j];
    }
    __syncthreads();

    // 4-way merge per query (lexicographic (key, idx) == top_k tie-break)
    if (t < 128) {
        int p[4] = {0, 0, 0, 0};
        int qg = gbase + qb + t;
#pragma unroll 1
        for (int k = 0; k < 16; k++) {
            float best = FINF; int bidx = 0x7fffffff; int bl = 0;
#pragma unroll
            for (int j = 0; j < 4; j++) {
                bool ok = p[j] < 16;
                float kv = ok ? dk[(t*4 + j)*16 + p[j]] : FINF;
                int   iv = ok ? di[(t*4 + j)*16 + p[j]] : 0x7fffffff;
                if (kv < best || (kv == best && iv < bidx)) { best = kv; bidx = iv; bl = j; }
            }
            p[bl]++;
            int sg = gbase + bidx;
            size_t e = (size_t)qg * KNB + k;
            d_nbr[e] = sg;
            if (we) { esrc[e] = (float)sg; edst[e] = (float)qg; }
        }
    }
}

// ---------------- split bf16 HMMA GEMM (3 passes): C = A @ W + bias ---------
#define GAP 80
#define GBP 272
#define AH0 0
#define AL0 10240
#define AH1 20480
#define AL1 30720
#define WH0 40960
#define WL0 49664
#define WH1 58368
#define WL1 67072
#define GSM 75776

__global__ __launch_bounds__(256)
void k_gemm(const __nv_bfloat16* __restrict__ Ahi, const __nv_bfloat16* __restrict__ Alo,
            const __nv_bfloat16* __restrict__ Whi, const __nv_bfloat16* __restrict__ Wlo,
            const float* __restrict__ bias, float* __restrict__ C,
            int Kd, int addBias) {
    extern __shared__ char sm[];
    const uint32_t smb = smem_u32(sm);
    const int t = threadIdx.x, w = t >> 5, lane = t & 31;
    const int nbb = blockIdx.x * 128, mb = blockIdx.y * 128;
    const int wm = (w >> 1) * 32, wn = (w & 1) * 64;
    const int nchunk = Kd / 32;

    for (int it = t; it < 512; it += 256) {
        int row = it >> 2, c = it & 3;
        cpa16(smb + AH0 + row*GAP + c*16, Ahi + (size_t)(mb + row)*Kd + c*8);
        cpa16(smb + AL0 + row*GAP + c*16, Alo + (size_t)(mb + row)*Kd + c*8);
    }
    for (int it = t; it < 512; it += 256) {
        int row = it >> 4, c = it & 15;
        cpa16(smb + WH0 + row*GBP + c*16, Whi + (size_t)row*OUTD + nbb + c*8);
        cpa16(smb + WL0 + row*GBP + c*16, Wlo + (size_t)row*OUTD + nbb + c*8);
    }
    cp_commit();

    float acc[2][8][4];
#pragma unroll
    for (int mt = 0; mt < 2; mt++)
#pragma unroll
        for (int nt = 0; nt < 8; nt++)
#pragma unroll
            for (int v = 0; v < 4; v++) acc[mt][nt][v] = 0.f;

    for (int i = 0; i < nchunk; i++) {
        cp_wait0();
        __syncthreads();
        if (i + 1 < nchunk) {
            uint32_t ah = ((i + 1) & 1) ? AH1 : AH0, al = ((i + 1) & 1) ? AL1 : AL0;
            uint32_t wh = ((i + 1) & 1) ? WH1 : WH0, wl = ((i + 1) & 1) ? WL1 : WL0;
            int kc = (i + 1) * 32;
            for (int it = t; it < 512; it += 256) {
                int row = it >> 2, c = it & 3;
                cpa16(smb + ah + row*GAP + c*16, Ahi + (size_t)(mb + row)*Kd + kc + c*8);
                cpa16(smb + al + row*GAP + c*16, Alo + (size_t)(mb + row)*Kd + kc + c*8);
            }
            for (int it = t; it < 512; it += 256) {
                int row = it >> 4, c = it & 15;
                cpa16(smb + wh + row*GBP + c*16, Whi + (size_t)(kc + row)*OUTD + nbb + c*8);
                cpa16(smb + wl + row*GBP + c*16, Wlo + (size_t)(kc + row)*OUTD + nbb + c*8);
            }
            cp_commit();
        }
        const uint32_t ah = smb + ((i & 1) ? AH1 : AH0), al = smb + ((i & 1) ? AL1 : AL0);
        const uint32_t wh = smb + ((i & 1) ? WH1 : WH0), wl = smb + ((i & 1) ? WL1 : WL0);
#pragma unroll
        for (int ks = 0; ks < 2; ks++) {
            uint32_t afh[2][4], afl[2][4];
#pragma unroll
            for (int mt = 0; mt < 2; mt++) {
                uint32_t aoff = (wm + mt*16 + (lane & 15))*GAP + ks*32 + (lane >> 4)*16;
                ldsm4(afh[mt], ah + aoff);
                ldsm4(afl[mt], al + aoff);
            }
#pragma unroll
            for (int nt = 0; nt < 8; nt++) {
                uint32_t boff = (ks*16 + (lane & 15))*GBP + (wn + nt*8)*2;
                uint32_t bfh[2], bfl[2];
                ldsm2t(bfh, wh + boff);
                ldsm2t(bfl, wl + boff);
#pragma unroll
                for (int mt = 0; mt < 2; mt++) {
                    mma16816(acc[mt][nt], afh[mt], bfh);
                    mma16816(acc[mt][nt], afh[mt], bfl);
                    mma16816(acc[mt][nt], afl[mt], bfh);
                }
            }
        }
    }
#pragma unroll
    for (int mt = 0; mt < 2; mt++) {
#pragma unroll
        for (int nt = 0; nt < 8; nt++) {
            int m0 = mb + wm + mt*16 + (lane >> 2);
            int n0 = nbb + wn + nt*8 + 2*(lane & 3);
            float b0 = addBias ? bias[n0] : 0.f;
            float b1 = addBias ? bias[n0 + 1] : 0.f;
            float2 v0 = make_float2(acc[mt][nt][0] + b0, acc[mt][nt][1] + b1);
            float2 v1 = make_float2(acc[mt][nt][2] + b0, acc[mt][nt][3] + b1);
            *(float2*)(C + (size_t)m0 * OUTD + n0) = v0;
            *(float2*)(C + (size_t)(m0 + 8) * OUTD + n0) = v1;
        }
    }
}

// ---------------- GCN aggregation (deg == 17 exactly) ----------------
__global__ __launch_bounds__(256) void k_agg_relu(const float* __restrict__ g,
                                                  const float* __restrict__ bias,
                                                  __nv_bfloat16* __restrict__ ohi,
                                                  __nv_bfloat16* __restrict__ olo) {
    const int node = blockIdx.x;
    const int t = threadIdx.x;
    __shared__ int nb_s[KNB];
    if (t < KNB) nb_s[t] = d_nbr[(size_t)node * KNB + t];
    __syncthreads();
    const float norm = 1.0f / 17.0f;
    float acc = 0.f;
#pragma unroll
    for (int k = 0; k < KNB; k++) acc += g[(size_t)nb_s[k] * OUTD + t] * norm;
    acc += g[(size_t)node * OUTD + t] * norm;
    acc += bias[t];
    acc = fmaxf(acc, 0.f);
    __nv_bfloat16 h = __float2bfloat16_rn(acc);
    ohi[(size_t)node * OUTD + t] = h;
    olo[(size_t)node * OUTD + t] = __float2bfloat16_rn(acc - __bfloat162float(h));
}
__global__ __launch_bounds__(256) void k_agg_final(const float* __restrict__ g,
                                                   const float* __restrict__ bias,
                                                   const float* __restrict__ sc,
                                                   float* __restrict__ out) {
    const int node = blockIdx.x;
    const int t = threadIdx.x;
    __shared__ int nb_s[KNB];
    if (t < KNB) nb_s[t] = d_nbr[(size_t)node * KNB + t];
    __syncthreads();
    const float norm = 1.0f / 17.0f;
    float acc = 0.f;
#pragma unroll
    for (int k = 0; k < KNB; k++) acc += g[(size_t)nb_s[k] * OUTD + t] * norm;
    acc += g[(size_t)node * OUTD + t] * norm;
    acc += bias[t];
    acc += sc[(size_t)node * OUTD + t];
    out[(size_t)node * OUTD + t] = acc;
}

// ---------------- launch ----------------
extern "C" void kernel_launch(void* const* d_in, const int* in_sizes, int n_in,
                              void* d_out, int out_size) {
    const float* x  = (const float*)d_in[0];
    const float* W1 = (const float*)d_in[2];
    const float* b1 = (const float*)d_in[3];
    const float* W2 = (const float*)d_in[4];
    const float* b2 = (const float*)d_in[5];
    const float* Ws = (const float*)d_in[6];
    const float* bs = (const float*)d_in[7];

    float* out  = (float*)d_out;
    float* esrc = out + (size_t)NTOT * OUTD;
    float* edst = esrc + NEDGE;
    int we = (out_size >= (int)((size_t)NTOT * OUTD + 2 * NEDGE)) ? 1 : 0;

    float *g1, *g2, *sc;
    __nv_bfloat16 *xhi, *xmd, *xlo, *h1hi, *h1lo;
    __nv_bfloat16 *w1hi, *w1lo, *w2hi, *w2lo, *wshi, *wslo;
    cudaGetSymbolAddress((void**)&g1, d_g1);
    cudaGetSymbolAddress((void**)&g2, d_g2);
    cudaGetSymbolAddress((void**)&sc, d_sc);
    cudaGetSymbolAddress((void**)&xhi, d_xhi);
    cudaGetSymbolAddress((void**)&xmd, d_xmd);
    cudaGetSymbolAddress((void**)&xlo, d_xlo);
    cudaGetSymbolAddress((void**)&h1hi, d_h1hi);
    cudaGetSymbolAddress((void**)&h1lo, d_h1lo);
    cudaGetSymbolAddress((void**)&w1hi, d_w1hi);
    cudaGetSymbolAddress((void**)&w1lo, d_w1lo);
    cudaGetSymbolAddress((void**)&w2hi, d_w2hi);
    cudaGetSymbolAddress((void**)&w2lo, d_w2lo);
    cudaGetSymbolAddress((void**)&wshi, d_wshi);
    cudaGetSymbolAddress((void**)&wslo, d_wslo);

    cudaFuncSetAttribute(k_knn, cudaFuncAttributeMaxDynamicSharedMemorySize, SMTOT);
    cudaFuncSetAttribute(k_gemm, cudaFuncAttributeMaxDynamicSharedMemorySize, GSM);

    k_sqn<<<(NTOT + 255) / 256, 256>>>(x);
    k_split3<<<(NTOT * IND / 4 + 255) / 256, 256>>>(x);
    k_splitw<<<(IND * OUTD + 255) / 256, 256>>>(W1, w1hi, w1lo, IND * OUTD);
    k_splitw<<<(OUTD * OUTD + 255) / 256, 256>>>(W2, w2hi, w2lo, OUTD * OUTD);
    k_splitw<<<(IND * OUTD + 255) / 256, 256>>>(Ws, wshi, wslo, IND * OUTD);

    k_knn<<<dim3(NN / 128, NB), 256, SMTOT>>>(xhi, xmd, xlo, esrc, edst, we);

    k_gemm<<<dim3(OUTD / 128, NTOT / 128), 256, GSM>>>(xhi, xmd, w1hi, w1lo, (const float*)0, g1, IND, 0);
    k_agg_relu<<<NTOT, 256>>>(g1, b1, h1hi, h1lo);
    k_gemm<<<dim3(OUTD / 128, NTOT / 128), 256, GSM>>>(h1hi, h1lo, w2hi, w2lo, (const float*)0, g2, OUTD, 0);
    k_gemm<<<dim3(OUTD / 128, NTOT / 128), 256, GSM>>>(xhi, xmd, wshi, wslo, bs, sc, IND, 1);
    k_agg_final<<<NTOT, 256>>>(g2, b2, sc, out);
}

// round 7
// speedup vs baseline: 1.4248x; 1.1617x over previous
#include <cuda_runtime.h>
#include <cuda_fp16.h>
#include <stdint.h>

#define NB 16
#define NN 2048
#define NTOT (NB*NN)
#define KNB 16
#define IND 128
#define OUTD 256
#define NEDGE (NTOT*KNB)

// ---------------- scratch ----------------
__device__ float d_sqn[NTOT];
__device__ int   d_nbr[NTOT*KNB];
__device__ float d_g1[(size_t)NTOT*OUTD];
__device__ float d_g2[(size_t)NTOT*OUTD];
__device__ float d_sc[(size_t)NTOT*OUTD];
__device__ __half d_xh[(size_t)NTOT*IND];
__device__ __half d_xl[(size_t)NTOT*IND];
__device__ __half d_h1h[(size_t)NTOT*OUTD];
__device__ __half d_h1l[(size_t)NTOT*OUTD];
__device__ __half d_w1h[IND*OUTD],  d_w1l[IND*OUTD];
__device__ __half d_w2h[OUTD*OUTD], d_w2l[OUTD*OUTD];
__device__ __half d_wsh[IND*OUTD],  d_wsl[IND*OUTD];

// ---------------- helpers ----------------
__device__ __forceinline__ uint32_t smem_u32(const void* p) {
    uint32_t a;
    asm("{ .reg .u64 t; cvta.to.shared.u64 t, %1; cvt.u32.u64 %0, t; }" : "=r"(a) : "l"(p));
    return a;
}
__device__ __forceinline__ void cpa16(uint32_t dst, const void* src) {
    asm volatile("cp.async.cg.shared.global [%0], [%1], 16;" :: "r"(dst), "l"(src));
}
__device__ __forceinline__ void cp_commit() { asm volatile("cp.async.commit_group;"); }
__device__ __forceinline__ void cp_wait0()  { asm volatile("cp.async.wait_group 0;"); }
__device__ __forceinline__ void ldsm4(uint32_t* r, uint32_t a) {
    asm volatile("ldmatrix.sync.aligned.m8n8.x4.shared.b16 {%0,%1,%2,%3}, [%4];"
        : "=r"(r[0]), "=r"(r[1]), "=r"(r[2]), "=r"(r[3]) : "r"(a));
}
__device__ __forceinline__ void ldsm2t(uint32_t* r, uint32_t a) {
    asm volatile("ldmatrix.sync.aligned.m8n8.x2.trans.shared.b16 {%0,%1}, [%2];"
        : "=r"(r[0]), "=r"(r[1]) : "r"(a));
}
__device__ __forceinline__ void mma16816(float* c, const uint32_t* a, const uint32_t* b) {
    asm volatile("mma.sync.aligned.m16n8k16.row.col.f32.f16.f16.f32 "
        "{%0,%1,%2,%3}, {%4,%5,%6,%7}, {%8,%9}, {%0,%1,%2,%3};"
        : "+f"(c[0]), "+f"(c[1]), "+f"(c[2]), "+f"(c[3])
        : "r"(a[0]), "r"(a[1]), "r"(a[2]), "r"(a[3]), "r"(b[0]), "r"(b[1]));
}

// ---------------- squared norms (fp32 exact) ----------------
__global__ void k_sqn(const float* __restrict__ x) {
    int i = blockIdx.x * blockDim.x + threadIdx.x;
    if (i >= NTOT) return;
    const float4* p = (const float4*)(x + (size_t)i * IND);
    float s = 0.f;
#pragma unroll
    for (int j = 0; j < IND/4; j++) {
        float4 v = p[j];
        s = fmaf(v.x, v.x, s); s = fmaf(v.y, v.y, s);
        s = fmaf(v.z, v.z, s); s = fmaf(v.w, v.w, s);
    }
    d_sqn[i] = s;
}

// ---------------- 2-way fp16 split of x ----------------
__global__ void k_split2(const float* __restrict__ x) {
    int i = blockIdx.x * blockDim.x + threadIdx.x;  // over NTOT*IND/4
    if (i >= NTOT * IND / 4) return;
    float4 v = ((const float4*)x)[i];
    float f[4] = {v.x, v.y, v.z, v.w};
    __half h[4], l[4];
#pragma unroll
    for (int j = 0; j < 4; j++) {
        h[j] = __float2half_rn(f[j]);
        l[j] = __float2half_rn(f[j] - __half2float(h[j]));
    }
    ((uint2*)d_xh)[i] = *(uint2*)h;
    ((uint2*)d_xl)[i] = *(uint2*)l;
}

// ---------------- 2-way fp16 split (weights) ----------------
__global__ void k_splitw(const float* __restrict__ s, __half* __restrict__ hi,
                         __half* __restrict__ lo, int n) {
    int i = blockIdx.x * blockDim.x + threadIdx.x;
    if (i >= n) return;
    float f = s[i];
    __half h = __float2half_rn(f);
    hi[i] = h;
    lo[i] = __float2half_rn(f - __half2float(h));
}

// ---------------- kNN via fp16 mma.sync (2-way split, 3 passes) -------------
#define PB 272                    // tile pitch bytes (136 fp16)
#define TQB (128*PB)              // 34816
#define TCB (64*PB)               // 17408
#define SQ 0
#define SC (2*TQB)                // cand: 2 buf x 2 split x TCB
#define SCSQ (SC + 4*TCB)
#define SMTOT (SCSQ + 2*64*4)
#define NCH (NN/64)               // 32 chunks

__device__ __forceinline__ void ins16(float* bd, int* bi, float key, int idx) {
    if (key < bd[15]) {
        bd[15] = key; bi[15] = idx;
#pragma unroll
        for (int j = 15; j > 0; j--) {
            if (bd[j] < bd[j-1]) {
                float tf = bd[j]; bd[j] = bd[j-1]; bd[j-1] = tf;
                int   ti = bi[j]; bi[j] = bi[j-1]; bi[j-1] = ti;
            }
        }
    }
}

__global__ __launch_bounds__(256)
void k_knn(const __half* __restrict__ xh, const __half* __restrict__ xl,
           float* __restrict__ esrc, float* __restrict__ edst, int we) {
    extern __shared__ char sm[];
    const uint32_t smb = smem_u32(sm);
    float* csq = (float*)(sm + SCSQ);
    const int t = threadIdx.x, w = t >> 5, lane = t & 31;
    const int b = blockIdx.y, qb = blockIdx.x * 128, gbase = b * NN;
    const float FINF = __int_as_float(0x7f800000);
    const __half* xs[2] = {xh, xl};

    // prologue: 2 query tiles + candidate chunk 0 (2 splits)
    for (int s = 0; s < 2; s++) {
        for (int it = t; it < 2048; it += 256) {
            int row = it >> 4, c = it & 15;
            cpa16(smb + SQ + s*TQB + row*PB + c*16,
                  xs[s] + ((size_t)(gbase + qb + row) << 7) + c*8);
        }
        for (int it = t; it < 1024; it += 256) {
            int row = it >> 4, c = it & 15;
            cpa16(smb + SC + s*TCB + row*PB + c*16,
                  xs[s] + ((size_t)(gbase + row) << 7) + c*8);
        }
    }
    if (t < 64) csq[t] = d_sqn[gbase + t];
    cp_commit();

    // per-lane top-16 lists: list0 -> row r0, list1 -> row r0+8
    const int r0 = w * 16 + (lane >> 2);
    const int quarter = lane & 3;
    float bd0[16], bd1[16]; int bi0[16], bi1[16];
#pragma unroll
    for (int j = 0; j < 16; j++) { bd0[j] = FINF; bd1[j] = FINF; bi0[j] = 0; bi1[j] = 0; }

    for (int i = 0; i < NCH; i++) {
        cp_wait0();
        __syncthreads();
        const int buf = i & 1;
        if (i + 1 < NCH) {
            const int nb_ = (i + 1) & 1, cb2 = (i + 1) * 64;
            for (int s = 0; s < 2; s++)
                for (int it = t; it < 1024; it += 256) {
                    int row = it >> 4, c = it & 15;
                    cpa16(smb + SC + (nb_*2 + s)*TCB + row*PB + c*16,
                          xs[s] + ((size_t)(gbase + cb2 + row) << 7) + c*8);
                }
            if (t < 64) csq[nb_ * 64 + t] = d_sqn[gbase + cb2 + t];
            cp_commit();
        }
        const uint32_t chB = smb + SC + (buf*2) * TCB;
        const float* cs = csq + buf * 64;
        const int cb = i * 64;

        float acc[8][4];
#pragma unroll
        for (int nt = 0; nt < 8; nt++)
#pragma unroll
            for (int v = 0; v < 4; v++) acc[nt][v] = 0.f;

#pragma unroll 2
        for (int ks = 0; ks < 8; ks++) {
            uint32_t afh[4], afl[4];
            uint32_t abase = smb + SQ + (w*16 + (lane & 15))*PB + ks*32 + (lane >> 4)*16;
            ldsm4(afh, abase);
            ldsm4(afl, abase + TQB);
            // B: 4 pairs of n8 tiles, each via ldsm4 (2 tiles/load)
#pragma unroll
            for (int p = 0; p < 4; p++) {
                uint32_t bbase = chB + (p*16 + (lane >> 4)*8 + (lane & 7))*PB
                               + ks*32 + ((lane >> 3) & 1)*16;
                uint32_t bh[4], bl[4];
                ldsm4(bh, bbase);
                ldsm4(bl, bbase + TCB);
                mma16816(acc[2*p],     afh, bh);        // hh
                mma16816(acc[2*p],     afh, bl);        // hl
                mma16816(acc[2*p],     afl, bh);        // lh
                mma16816(acc[2*p + 1], afh, bh + 2);
                mma16816(acc[2*p + 1], afh, bl + 2);
                mma16816(acc[2*p + 1], afl, bh + 2);
            }
        }
        // selection from fragments
#pragma unroll
        for (int nt = 0; nt < 8; nt++) {
            int cl = nt*8 + 2*quarter;
            float cq0 = cs[cl], cq1 = cs[cl + 1];
            float k00 = fmaf(-2.f, acc[nt][0], cq0);
            float k01 = fmaf(-2.f, acc[nt][1], cq1);
            float k10 = fmaf(-2.f, acc[nt][2], cq0);
            float k11 = fmaf(-2.f, acc[nt][3], cq1);
            int ci = cb + cl;
            if (qb + r0 == ci)         k00 = FINF;
            if (qb + r0 == ci + 1)     k01 = FINF;
            if (qb + r0 + 8 == ci)     k10 = FINF;
            if (qb + r0 + 8 == ci + 1) k11 = FINF;
            ins16(bd0, bi0, k00, ci);
            ins16(bd0, bi0, k01, ci + 1);
            ins16(bd1, bi1, k10, ci);
            ins16(bd1, bi1, k11, ci + 1);
        }
    }
    __syncthreads();

    // dump 4 lists/query (reuse candidate area)
    float* dk = (float*)(sm + SC);
    int*   di = (int*)(sm + SC + 32768);
#pragma unroll
    for (int j = 0; j < 16; j++) {
        dk[(r0*4 + quarter)*16 + j] = bd0[j];
        di[(r0*4 + quarter)*16 + j] = bi0[j];
        dk[((r0 + 8)*4 + quarter)*16 + j] = bd1[j];
        di[((r0 + 8)*4 + quarter)*16 + j] = bi1[j];
    }
    __syncthreads();

    // 4-way merge per query (lexicographic (key, idx) == top_k tie-break)
    if (t < 128) {
        int p[4] = {0, 0, 0, 0};
        int qg = gbase + qb + t;
#pragma unroll 1
        for (int k = 0; k < 16; k++) {
            float best = FINF; int bidx = 0x7fffffff; int bl = 0;
#pragma unroll
            for (int j = 0; j < 4; j++) {
                bool ok = p[j] < 16;
                float kv = ok ? dk[(t*4 + j)*16 + p[j]] : FINF;
                int   iv = ok ? di[(t*4 + j)*16 + p[j]] : 0x7fffffff;
                if (kv < best || (kv == best && iv < bidx)) { best = kv; bidx = iv; bl = j; }
            }
            p[bl]++;
            int sg = gbase + bidx;
            size_t e = (size_t)qg * KNB + k;
            d_nbr[e] = sg;
            if (we) { esrc[e] = (float)sg; edst[e] = (float)qg; }
        }
    }
}

// ---------------- split fp16 HMMA GEMM (3 passes): C = A @ W + bias ---------
#define GAP 80
#define GBP 272
#define AH0 0
#define AL0 10240
#define AH1 20480
#define AL1 30720
#define WH0 40960
#define WL0 49664
#define WH1 58368
#define WL1 67072
#define GSM 75776

__global__ __launch_bounds__(256)
void k_gemm(const __half* __restrict__ Ahi, const __half* __restrict__ Alo,
            const __half* __restrict__ Whi, const __half* __restrict__ Wlo,
            const float* __restrict__ bias, float* __restrict__ C,
            int Kd, int addBias) {
    extern __shared__ char sm[];
    const uint32_t smb = smem_u32(sm);
    const int t = threadIdx.x, w = t >> 5, lane = t & 31;
    const int nbb = blockIdx.x * 128, mb = blockIdx.y * 128;
    const int wm = (w >> 1) * 32, wn = (w & 1) * 64;
    const int nchunk = Kd / 32;

    for (int it = t; it < 512; it += 256) {
        int row = it >> 2, c = it & 3;
        cpa16(smb + AH0 + row*GAP + c*16, Ahi + (size_t)(mb + row)*Kd + c*8);
        cpa16(smb + AL0 + row*GAP + c*16, Alo + (size_t)(mb + row)*Kd + c*8);
    }
    for (int it = t; it < 512; it += 256) {
        int row = it >> 4, c = it & 15;
        cpa16(smb + WH0 + row*GBP + c*16, Whi + (size_t)row*OUTD + nbb + c*8);
        cpa16(smb + WL0 + row*GBP + c*16, Wlo + (size_t)row*OUTD + nbb + c*8);
    }
    cp_commit();

    float acc[2][8][4];
#pragma unroll
    for (int mt = 0; mt < 2; mt++)
#pragma unroll
        for (int nt = 0; nt < 8; nt++)
#pragma unroll
            for (int v = 0; v < 4; v++) acc[mt][nt][v] = 0.f;

    for (int i = 0; i < nchunk; i++) {
        cp_wait0();
        __syncthreads();
        if (i + 1 < nchunk) {
            uint32_t ah = ((i + 1) & 1) ? AH1 : AH0, al = ((i + 1) & 1) ? AL1 : AL0;
            uint32_t wh = ((i + 1) & 1) ? WH1 : WH0, wl = ((i + 1) & 1) ? WL1 : WL0;
            int kc = (i + 1) * 32;
            for (int it = t; it < 512; it += 256) {
                int row = it >> 2, c = it & 3;
                cpa16(smb + ah + row*GAP + c*16, Ahi + (size_t)(mb + row)*Kd + kc + c*8);
                cpa16(smb + al + row*GAP + c*16, Alo + (size_t)(mb + row)*Kd + kc + c*8);
            }
            for (int it = t; it < 512; it += 256) {
                int row = it >> 4, c = it & 15;
                cpa16(smb + wh + row*GBP + c*16, Whi + (size_t)(kc + row)*OUTD + nbb + c*8);
                cpa16(smb + wl + row*GBP + c*16, Wlo + (size_t)(kc + row)*OUTD + nbb + c*8);
            }
            cp_commit();
        }
        const uint32_t ah = smb + ((i & 1) ? AH1 : AH0), al = smb + ((i & 1) ? AL1 : AL0);
        const uint32_t wh = smb + ((i & 1) ? WH1 : WH0), wl = smb + ((i & 1) ? WL1 : WL0);
#pragma unroll
        for (int ks = 0; ks < 2; ks++) {
            uint32_t afh[2][4], afl[2][4];
#pragma unroll
            for (int mt = 0; mt < 2; mt++) {
                uint32_t aoff = (wm + mt*16 + (lane & 15))*GAP + ks*32 + (lane >> 4)*16;
                ldsm4(afh[mt], ah + aoff);
                ldsm4(afl[mt], al + aoff);
            }
#pragma unroll
            for (int nt = 0; nt < 8; nt++) {
                uint32_t boff = (ks*16 + (lane & 15))*GBP + (wn + nt*8)*2;
                uint32_t bfh[2], bfl[2];
                ldsm2t(bfh, wh + boff);
                ldsm2t(bfl, wl + boff);
#pragma unroll
                for (int mt = 0; mt < 2; mt++) {
                    mma16816(acc[mt][nt], afh[mt], bfh);
                    mma16816(acc[mt][nt], afh[mt], bfl);
                    mma16816(acc[mt][nt], afl[mt], bfh);
                }
            }
        }
    }
#pragma unroll
    for (int mt = 0; mt < 2; mt++) {
#pragma unroll
        for (int nt = 0; nt < 8; nt++) {
            int m0 = mb + wm + mt*16 + (lane >> 2);
            int n0 = nbb + wn + nt*8 + 2*(lane & 3);
            float b0 = addBias ? bias[n0] : 0.f;
            float b1 = addBias ? bias[n0 + 1] : 0.f;
            float2 v0 = make_float2(acc[mt][nt][0] + b0, acc[mt][nt][1] + b1);
            float2 v1 = make_float2(acc[mt][nt][2] + b0, acc[mt][nt][3] + b1);
            *(float2*)(C + (size_t)m0 * OUTD + n0) = v0;
            *(float2*)(C + (size_t)(m0 + 8) * OUTD + n0) = v1;
        }
    }
}

// ---------------- GCN aggregation (deg == 17 exactly) ----------------
__global__ __launch_bounds__(256) void k_agg_relu(const float* __restrict__ g,
                                                  const float* __restrict__ bias,
                                                  __half* __restrict__ ohi,
                                                  __half* __restrict__ olo) {
    const int node = blockIdx.x;
    const int t = threadIdx.x;
    __shared__ int nb_s[KNB];
    if (t < KNB) nb_s[t] = d_nbr[(size_t)node * KNB + t];
    __syncthreads();
    const float norm = 1.0f / 17.0f;
    float acc = 0.f;
#pragma unroll
    for (int k = 0; k < KNB; k++) acc += g[(size_t)nb_s[k] * OUTD + t] * norm;
    acc += g[(size_t)node * OUTD + t] * norm;
    acc += bias[t];
    acc = fmaxf(acc, 0.f);
    __half h = __float2half_rn(acc);
    ohi[(size_t)node * OUTD + t] = h;
    olo[(size_t)node * OUTD + t] = __float2half_rn(acc - __half2float(h));
}
__global__ __launch_bounds__(256) void k_agg_final(const float* __restrict__ g,
                                                   const float* __restrict__ bias,
                                                   const float* __restrict__ sc,
                                                   float* __restrict__ out) {
    const int node = blockIdx.x;
    const int t = threadIdx.x;
    __shared__ int nb_s[KNB];
    if (t < KNB) nb_s[t] = d_nbr[(size_t)node * KNB + t];
    __syncthreads();
    const float norm = 1.0f / 17.0f;
    float acc = 0.f;
#pragma unroll
    for (int k = 0; k < KNB; k++) acc += g[(size_t)nb_s[k] * OUTD + t] * norm;
    acc += g[(size_t)node * OUTD + t] * norm;
    acc += bias[t];
    acc += sc[(size_t)node * OUTD + t];
    out[(size_t)node * OUTD + t] = acc;
}

// ---------------- launch ----------------
extern "C" void kernel_launch(void* const* d_in, const int* in_sizes, int n_in,
                              void* d_out, int out_size) {
    const float* x  = (const float*)d_in[0];
    const float* W1 = (const float*)d_in[2];
    const float* b1 = (const float*)d_in[3];
    const float* W2 = (const float*)d_in[4];
    const float* b2 = (const float*)d_in[5];
    const float* Ws = (const float*)d_in[6];
    const float* bs = (const float*)d_in[7];

    float* out  = (float*)d_out;
    float* esrc = out + (size_t)NTOT * OUTD;
    float* edst = esrc + NEDGE;
    int we = (out_size >= (int)((size_t)NTOT * OUTD + 2 * NEDGE)) ? 1 : 0;

    float *g1, *g2, *sc;
    __half *xh, *xl, *h1h, *h1l, *w1h, *w1l, *w2h, *w2l, *wsh, *wsl;
    cudaGetSymbolAddress((void**)&g1, d_g1);
    cudaGetSymbolAddress((void**)&g2, d_g2);
    cudaGetSymbolAddress((void**)&sc, d_sc);
    cudaGetSymbolAddress((void**)&xh, d_xh);
    cudaGetSymbolAddress((void**)&xl, d_xl);
    cudaGetSymbolAddress((void**)&h1h, d_h1h);
    cudaGetSymbolAddress((void**)&h1l, d_h1l);
    cudaGetSymbolAddress((void**)&w1h, d_w1h);
    cudaGetSymbolAddress((void**)&w1l, d_w1l);
    cudaGetSymbolAddress((void**)&w2h, d_w2h);
    cudaGetSymbolAddress((void**)&w2l, d_w2l);
    cudaGetSymbolAddress((void**)&wsh, d_wsh);
    cudaGetSymbolAddress((void**)&wsl, d_wsl);

    cudaFuncSetAttribute(k_knn, cudaFuncAttributeMaxDynamicSharedMemorySize, SMTOT);
    cudaFuncSetAttribute(k_gemm, cudaFuncAttributeMaxDynamicSharedMemorySize, GSM);

    // launch order chosen so k_knn is launch index 5 (ncu -s 5 -c 1 captures it)
    k_splitw<<<(IND * OUTD + 255) / 256, 256>>>(W1, w1h, w1l, IND * OUTD);
    k_splitw<<<(OUTD * OUTD + 255) / 256, 256>>>(W2, w2h, w2l, OUTD * OUTD);
    k_splitw<<<(IND * OUTD + 255) / 256, 256>>>(Ws, wsh, wsl, IND * OUTD);
    k_sqn<<<(NTOT + 255) / 256, 256>>>(x);
    k_split2<<<(NTOT * IND / 4 + 255) / 256, 256>>>(x);

    k_knn<<<dim3(NN / 128, NB), 256, SMTOT>>>(xh, xl, esrc, edst, we);

    k_gemm<<<dim3(OUTD / 128, NTOT / 128), 256, GSM>>>(xh, xl, w1h, w1l, (const float*)0, g1, IND, 0);
    k_agg_relu<<<NTOT, 256>>>(g1, b1, h1h, h1l);
    k_gemm<<<dim3(OUTD / 128, NTOT / 128), 256, GSM>>>(h1h, h1l, w2h, w2l, (const float*)0, g2, OUTD, 0);
    k_gemm<<<dim3(OUTD / 128, NTOT / 128), 256, GSM>>>(xh, xl, wsh, wsl, bs, sc, IND, 1);
    k_agg_final<<<NTOT, 256>>>(g2, b2, sc, out);
}

// round 8
// speedup vs baseline: 1.4498x; 1.0175x over previous
#include <cuda_runtime.h>
#include <cuda_fp16.h>
#include <stdint.h>

#define NB 16
#define NN 2048
#define NTOT (NB*NN)
#define KNB 16
#define IND 128
#define OUTD 256
#define NEDGE (NTOT*KNB)

// ---------------- scratch ----------------
__device__ float d_sqn[NTOT];
__device__ int   d_nbr[NTOT*KNB];
__device__ __half d_xh[(size_t)NTOT*IND];
__device__ __half d_xl[(size_t)NTOT*IND];
__device__ __half d_axh[(size_t)NTOT*IND];
__device__ __half d_axl[(size_t)NTOT*IND];
__device__ __half d_h1h[(size_t)NTOT*OUTD];
__device__ __half d_h1l[(size_t)NTOT*OUTD];
__device__ __half d_ahh[(size_t)NTOT*OUTD];
__device__ __half d_ahl[(size_t)NTOT*OUTD];
__device__ __half d_w1h[IND*OUTD],  d_w1l[IND*OUTD];
__device__ __half d_w2h[OUTD*OUTD], d_w2l[OUTD*OUTD];
__device__ __half d_wsh[IND*OUTD],  d_wsl[IND*OUTD];

// ---------------- helpers ----------------
__device__ __forceinline__ uint32_t smem_u32(const void* p) {
    uint32_t a;
    asm("{ .reg .u64 t; cvta.to.shared.u64 t, %1; cvt.u32.u64 %0, t; }" : "=r"(a) : "l"(p));
    return a;
}
__device__ __forceinline__ void cpa16(uint32_t dst, const void* src) {
    asm volatile("cp.async.cg.shared.global [%0], [%1], 16;" :: "r"(dst), "l"(src));
}
__device__ __forceinline__ void cp_commit() { asm volatile("cp.async.commit_group;"); }
__device__ __forceinline__ void cp_wait0()  { asm volatile("cp.async.wait_group 0;"); }
__device__ __forceinline__ void ldsm4(uint32_t* r, uint32_t a) {
    asm volatile("ldmatrix.sync.aligned.m8n8.x4.shared.b16 {%0,%1,%2,%3}, [%4];"
        : "=r"(r[0]), "=r"(r[1]), "=r"(r[2]), "=r"(r[3]) : "r"(a));
}
__device__ __forceinline__ void ldsm2t(uint32_t* r, uint32_t a) {
    asm volatile("ldmatrix.sync.aligned.m8n8.x2.trans.shared.b16 {%0,%1}, [%2];"
        : "=r"(r[0]), "=r"(r[1]) : "r"(a));
}
__device__ __forceinline__ void mma16816(float* c, const uint32_t* a, const uint32_t* b) {
    asm volatile("mma.sync.aligned.m16n8k16.row.col.f32.f16.f16.f32 "
        "{%0,%1,%2,%3}, {%4,%5,%6,%7}, {%8,%9}, {%0,%1,%2,%3};"
        : "+f"(c[0]), "+f"(c[1]), "+f"(c[2]), "+f"(c[3])
        : "r"(a[0]), "r"(a[1]), "r"(a[2]), "r"(a[3]), "r"(b[0]), "r"(b[1]));
}

// ---------------- prep: sqn + 2-way fp16 split of x (one pass) --------------
__global__ __launch_bounds__(256) void k_prep(const float* __restrict__ x) {
    const int row = blockIdx.x * 8 + (threadIdx.x >> 5);
    const int lane = threadIdx.x & 31;
    float4 v = *(const float4*)(x + (size_t)row * IND + lane * 4);
    float s = v.x*v.x + v.y*v.y + v.z*v.z + v.w*v.w;
#pragma unroll
    for (int o = 16; o > 0; o >>= 1) s += __shfl_xor_sync(0xffffffffu, s, o);
    if (lane == 0) d_sqn[row] = s;
    float f[4] = {v.x, v.y, v.z, v.w};
    __half h[4], l[4];
#pragma unroll
    for (int j = 0; j < 4; j++) {
        h[j] = __float2half_rn(f[j]);
        l[j] = __float2half_rn(f[j] - __half2float(h[j]));
    }
    const size_t o = (size_t)row * IND + lane * 4;
    *(uint2*)(d_xh + o) = *(uint2*)h;
    *(uint2*)(d_xl + o) = *(uint2*)l;
}

// ---------------- 2-way fp16 split (weights) ----------------
__global__ void k_splitw(const float* __restrict__ s, __half* __restrict__ hi,
                         __half* __restrict__ lo, int n) {
    int i = blockIdx.x * blockDim.x + threadIdx.x;
    if (i >= n) return;
    float f = s[i];
    __half h = __float2half_rn(f);
    hi[i] = h;
    lo[i] = __float2half_rn(f - __half2float(h));
}

// ---------------- kNN via fp16 mma.sync (2-way split, 3 passes) -------------
#define PB 272
#define TQB (128*PB)
#define TCB (64*PB)
#define SQ 0
#define SC (2*TQB)
#define SCSQ (SC + 4*TCB)
#define SMTOT (SCSQ + 2*64*4)
#define NCH (NN/64)

__device__ __forceinline__ void ins16(float* bd, int* bi, float key, int idx) {
    if (key < bd[15]) {
        bd[15] = key; bi[15] = idx;
#pragma unroll
        for (int j = 15; j > 0; j--) {
            if (bd[j] < bd[j-1]) {
                float tf = bd[j]; bd[j] = bd[j-1]; bd[j-1] = tf;
                int   ti = bi[j]; bi[j] = bi[j-1]; bi[j-1] = ti;
            }
        }
    }
}

__global__ __launch_bounds__(256)
void k_knn(const __half* __restrict__ xh, const __half* __restrict__ xl,
           float* __restrict__ esrc, float* __restrict__ edst, int we) {
    extern __shared__ char sm[];
    const uint32_t smb = smem_u32(sm);
    float* csq = (float*)(sm + SCSQ);
    const int t = threadIdx.x, w = t >> 5, lane = t & 31;
    const int b = blockIdx.y, qb = blockIdx.x * 128, gbase = b * NN;
    const float FINF = __int_as_float(0x7f800000);
    const __half* xs[2] = {xh, xl};

    for (int s = 0; s < 2; s++) {
        for (int it = t; it < 2048; it += 256) {
            int row = it >> 4, c = it & 15;
            cpa16(smb + SQ + s*TQB + row*PB + c*16,
                  xs[s] + ((size_t)(gbase + qb + row) << 7) + c*8);
        }
        for (int it = t; it < 1024; it += 256) {
            int row = it >> 4, c = it & 15;
            cpa16(smb + SC + s*TCB + row*PB + c*16,
                  xs[s] + ((size_t)(gbase + row) << 7) + c*8);
        }
    }
    if (t < 64) csq[t] = d_sqn[gbase + t];
    cp_commit();

    const int r0 = w * 16 + (lane >> 2);
    const int quarter = lane & 3;
    float bd0[16], bd1[16]; int bi0[16], bi1[16];
#pragma unroll
    for (int j = 0; j < 16; j++) { bd0[j] = FINF; bd1[j] = FINF; bi0[j] = 0; bi1[j] = 0; }

    for (int i = 0; i < NCH; i++) {
        cp_wait0();
        __syncthreads();
        const int buf = i & 1;
        if (i + 1 < NCH) {
            const int nb_ = (i + 1) & 1, cb2 = (i + 1) * 64;
            for (int s = 0; s < 2; s++)
                for (int it = t; it < 1024; it += 256) {
                    int row = it >> 4, c = it & 15;
                    cpa16(smb + SC + (nb_*2 + s)*TCB + row*PB + c*16,
                          xs[s] + ((size_t)(gbase + cb2 + row) << 7) + c*8);
                }
            if (t < 64) csq[nb_ * 64 + t] = d_sqn[gbase + cb2 + t];
            cp_commit();
        }
        const uint32_t chB = smb + SC + (buf*2) * TCB;
        const float* cs = csq + buf * 64;
        const int cb = i * 64;

        float acc[8][4];
#pragma unroll
        for (int nt = 0; nt < 8; nt++)
#pragma unroll
            for (int v = 0; v < 4; v++) acc[nt][v] = 0.f;

#pragma unroll 2
        for (int ks = 0; ks < 8; ks++) {
            uint32_t afh[4], afl[4];
            uint32_t abase = smb + SQ + (w*16 + (lane & 15))*PB + ks*32 + (lane >> 4)*16;
            ldsm4(afh, abase);
            ldsm4(afl, abase + TQB);
#pragma unroll
            for (int p = 0; p < 4; p++) {
                uint32_t bbase = chB + (p*16 + (lane >> 4)*8 + (lane & 7))*PB
                               + ks*32 + ((lane >> 3) & 1)*16;
                uint32_t bh[4], bl[4];
                ldsm4(bh, bbase);
                ldsm4(bl, bbase + TCB);
                mma16816(acc[2*p],     afh, bh);
                mma16816(acc[2*p],     afh, bl);
                mma16816(acc[2*p],     afl, bh);
                mma16816(acc[2*p + 1], afh, bh + 2);
                mma16816(acc[2*p + 1], afh, bl + 2);
                mma16816(acc[2*p + 1], afl, bh + 2);
            }
        }
#pragma unroll
        for (int nt = 0; nt < 8; nt++) {
            int cl = nt*8 + 2*quarter;
            float cq0 = cs[cl], cq1 = cs[cl + 1];
            float k00 = fmaf(-2.f, acc[nt][0], cq0);
            float k01 = fmaf(-2.f, acc[nt][1], cq1);
            float k10 = fmaf(-2.f, acc[nt][2], cq0);
            float k11 = fmaf(-2.f, acc[nt][3], cq1);
            int ci = cb + cl;
            if (qb + r0 == ci)         k00 = FINF;
            if (qb + r0 == ci + 1)     k01 = FINF;
            if (qb + r0 + 8 == ci)     k10 = FINF;
            if (qb + r0 + 8 == ci + 1) k11 = FINF;
            ins16(bd0, bi0, k00, ci);
            ins16(bd0, bi0, k01, ci + 1);
            ins16(bd1, bi1, k10, ci);
            ins16(bd1, bi1, k11, ci + 1);
        }
    }
    __syncthreads();

    float* dk = (float*)(sm + SC);
    int*   di = (int*)(sm + SC + 32768);
#pragma unroll
    for (int j = 0; j < 16; j++) {
        dk[(r0*4 + quarter)*16 + j] = bd0[j];
        di[(r0*4 + quarter)*16 + j] = bi0[j];
        dk[((r0 + 8)*4 + quarter)*16 + j] = bd1[j];
        di[((r0 + 8)*4 + quarter)*16 + j] = bi1[j];
    }
    __syncthreads();

    if (t < 128) {
        int p[4] = {0, 0, 0, 0};
        int qg = gbase + qb + t;
#pragma unroll 1
        for (int k = 0; k < 16; k++) {
            float best = FINF; int bidx = 0x7fffffff; int bl = 0;
#pragma unroll
            for (int j = 0; j < 4; j++) {
                bool ok = p[j] < 16;
                float kv = ok ? dk[(t*4 + j)*16 + p[j]] : FINF;
                int   iv = ok ? di[(t*4 + j)*16 + p[j]] : 0x7fffffff;
                if (kv < best || (kv == best && iv < bidx)) { best = kv; bidx = iv; bl = j; }
            }
            p[bl]++;
            int sg = gbase + bidx;
            size_t e = (size_t)qg * KNB + k;
            d_nbr[e] = sg;
            if (we) { esrc[e] = (float)sg; edst[e] = (float)qg; }
        }
    }
}

// ---------------- agg(x): 128-dim fp32 gather -> fp16 split pair ------------
__global__ __launch_bounds__(128) void k_aggx(const float* __restrict__ x,
                                              __half* __restrict__ oh,
                                              __half* __restrict__ ol) {
    const int node = blockIdx.x;
    const int t = threadIdx.x;
    __shared__ int nb_s[KNB];
    if (t < KNB) nb_s[t] = d_nbr[(size_t)node * KNB + t];
    __syncthreads();
    const float norm = 1.0f / 17.0f;
    float acc = 0.f;
#pragma unroll
    for (int k = 0; k < KNB; k++) acc += x[(size_t)nb_s[k] * IND + t] * norm;
    acc += x[(size_t)node * IND + t] * norm;
    __half h = __float2half_rn(acc);
    oh[(size_t)node * IND + t] = h;
    ol[(size_t)node * IND + t] = __float2half_rn(acc - __half2float(h));
}

// ---------------- agg(h1): 256-dim fp16-pair gather -> fp16 split pair ------
__global__ __launch_bounds__(256) void k_aggh(const __half* __restrict__ gh,
                                              const __half* __restrict__ gl,
                                              __half* __restrict__ oh,
                                              __half* __restrict__ ol) {
    const int node = blockIdx.x;
    const int t = threadIdx.x;
    __shared__ int nb_s[KNB];
    if (t < KNB) nb_s[t] = d_nbr[(size_t)node * KNB + t];
    __syncthreads();
    const float norm = 1.0f / 17.0f;
    float acc = 0.f;
#pragma unroll
    for (int k = 0; k < KNB; k++) {
        size_t o = (size_t)nb_s[k] * OUTD + t;
        acc += (__half2float(gh[o]) + __half2float(gl[o])) * norm;
    }
    {
        size_t o = (size_t)node * OUTD + t;
        acc += (__half2float(gh[o]) + __half2float(gl[o])) * norm;
    }
    __half h = __float2half_rn(acc);
    oh[(size_t)node * OUTD + t] = h;
    ol[(size_t)node * OUTD + t] = __float2half_rn(acc - __half2float(h));
}

// ---------------- GEMM smem layout ----------------
#define GAP 80
#define GBP 272
#define AH0 0
#define AL0 10240
#define AH1 20480
#define AL1 30720
#define WH0 40960
#define WL0 49664
#define WH1 58368
#define WL1 67072
#define GSM 75776

// ---------------- GEMM1: h1 = relu(ax@W1 + b1) -> fp16 pair -----------------
__global__ __launch_bounds__(256)
void k_gemm1(const __half* __restrict__ Ahi, const __half* __restrict__ Alo,
             const __half* __restrict__ Whi, const __half* __restrict__ Wlo,
             const float* __restrict__ bias,
             __half* __restrict__ Ch, __half* __restrict__ Cl) {
    extern __shared__ char sm[];
    const uint32_t smb = smem_u32(sm);
    const int t = threadIdx.x, w = t >> 5, lane = t & 31;
    const int nbb = blockIdx.x * 128, mb = blockIdx.y * 128;
    const int wm = (w >> 1) * 32, wn = (w & 1) * 64;
    const int Kd = IND, nchunk = IND / 32;

    for (int it = t; it < 512; it += 256) {
        int row = it >> 2, c = it & 3;
        cpa16(smb + AH0 + row*GAP + c*16, Ahi + (size_t)(mb + row)*Kd + c*8);
        cpa16(smb + AL0 + row*GAP + c*16, Alo + (size_t)(mb + row)*Kd + c*8);
    }
    for (int it = t; it < 512; it += 256) {
        int row = it >> 4, c = it & 15;
        cpa16(smb + WH0 + row*GBP + c*16, Whi + (size_t)row*OUTD + nbb + c*8);
        cpa16(smb + WL0 + row*GBP + c*16, Wlo + (size_t)row*OUTD + nbb + c*8);
    }
    cp_commit();

    float acc[2][8][4];
#pragma unroll
    for (int mt = 0; mt < 2; mt++)
#pragma unroll
        for (int nt = 0; nt < 8; nt++)
#pragma unroll
            for (int v = 0; v < 4; v++) acc[mt][nt][v] = 0.f;

    for (int i = 0; i < nchunk; i++) {
        cp_wait0();
        __syncthreads();
        if (i + 1 < nchunk) {
            uint32_t ah = ((i + 1) & 1) ? AH1 : AH0, al = ((i + 1) & 1) ? AL1 : AL0;
            uint32_t wh = ((i + 1) & 1) ? WH1 : WH0, wl = ((i + 1) & 1) ? WL1 : WL0;
            int kc = (i + 1) * 32;
            for (int it = t; it < 512; it += 256) {
                int row = it >> 2, c = it & 3;
                cpa16(smb + ah + row*GAP + c*16, Ahi + (size_t)(mb + row)*Kd + kc + c*8);
                cpa16(smb + al + row*GAP + c*16, Alo + (size_t)(mb + row)*Kd + kc + c*8);
            }
            for (int it = t; it < 512; it += 256) {
                int row = it >> 4, c = it & 15;
                cpa16(smb + wh + row*GBP + c*16, Whi + (size_t)(kc + row)*OUTD + nbb + c*8);
                cpa16(smb + wl + row*GBP + c*16, Wlo + (size_t)(kc + row)*OUTD + nbb + c*8);
            }
            cp_commit();
        }
        const uint32_t ah = smb + ((i & 1) ? AH1 : AH0), al = smb + ((i & 1) ? AL1 : AL0);
        const uint32_t wh = smb + ((i & 1) ? WH1 : WH0), wl = smb + ((i & 1) ? WL1 : WL0);
#pragma unroll
        for (int ks = 0; ks < 2; ks++) {
            uint32_t afh[2][4], afl[2][4];
#pragma unroll
            for (int mt = 0; mt < 2; mt++) {
                uint32_t aoff = (wm + mt*16 + (lane & 15))*GAP + ks*32 + (lane >> 4)*16;
                ldsm4(afh[mt], ah + aoff);
                ldsm4(afl[mt], al + aoff);
            }
#pragma unroll
            for (int nt = 0; nt < 8; nt++) {
                uint32_t boff = (ks*16 + (lane & 15))*GBP + (wn + nt*8)*2;
                uint32_t bfh[2], bfl[2];
                ldsm2t(bfh, wh + boff);
                ldsm2t(bfl, wl + boff);
#pragma unroll
                for (int mt = 0; mt < 2; mt++) {
                    mma16816(acc[mt][nt], afh[mt], bfh);
                    mma16816(acc[mt][nt], afh[mt], bfl);
                    mma16816(acc[mt][nt], afl[mt], bfh);
                }
            }
        }
    }
#pragma unroll
    for (int mt = 0; mt < 2; mt++) {
#pragma unroll
        for (int nt = 0; nt < 8; nt++) {
            int m0 = mb + wm + mt*16 + (lane >> 2);
            int n0 = nbb + wn + nt*8 + 2*(lane & 3);
            float b0 = bias[n0], b1v = bias[n0 + 1];
#pragma unroll
            for (int rr = 0; rr < 2; rr++) {
                int m = m0 + rr * 8;
                float v0 = fmaxf(acc[mt][nt][rr*2 + 0] + b0, 0.f);
                float v1 = fmaxf(acc[mt][nt][rr*2 + 1] + b1v, 0.f);
                __half h0 = __float2half_rn(v0), h1 = __float2half_rn(v1);
                __half l0 = __float2half_rn(v0 - __half2float(h0));
                __half l1 = __float2half_rn(v1 - __half2float(h1));
                __half2 hh; hh.x = h0; hh.y = h1;
                __half2 ll; ll.x = l0; ll.y = l1;
                *(__half2*)(Ch + (size_t)m * OUTD + n0) = hh;
                *(__half2*)(Cl + (size_t)m * OUTD + n0) = ll;
            }
        }
    }
}

// ---------------- GEMM2: out = ah@W2 + x@Ws + (b2+bs) -----------------------
__global__ __launch_bounds__(256)
void k_gemm2(const __half* __restrict__ A1h, const __half* __restrict__ A1l,
             const __half* __restrict__ W1h_, const __half* __restrict__ W1l_,
             const __half* __restrict__ A2h, const __half* __restrict__ A2l,
             const __half* __restrict__ W2h_, const __half* __restrict__ W2l_,
             const float* __restrict__ bias1, const float* __restrict__ bias2,
             float* __restrict__ C) {
    extern __shared__ char sm[];
    const uint32_t smb = smem_u32(sm);
    const int t = threadIdx.x, w = t >> 5, lane = t & 31;
    const int nbb = blockIdx.x * 128, mb = blockIdx.y * 128;
    const int wm = (w >> 1) * 32, wn = (w & 1) * 64;
    const int NC1 = OUTD / 32;                  // 8 chunks phase 1 (K=256)
    const int NC = NC1 + IND / 32;              // + 4 chunks phase 2 (K=128)

    // prefetch chunk j into buffer pb (0/1)
    auto prefetch = [&](int j, int pb) {
        uint32_t ah = pb ? AH1 : AH0, al = pb ? AL1 : AL0;
        uint32_t wh = pb ? WH1 : WH0, wl = pb ? WL1 : WL0;
        const __half *Ah, *Al, *Wh, *Wl;
        int Kd, kc;
        if (j < NC1) { Ah = A1h; Al = A1l; Wh = W1h_; Wl = W1l_; Kd = OUTD; kc = j * 32; }
        else         { Ah = A2h; Al = A2l; Wh = W2h_; Wl = W2l_; Kd = IND;  kc = (j - NC1) * 32; }
        for (int it = t; it < 512; it += 256) {
            int row = it >> 2, c = it & 3;
            cpa16(smb + ah + row*GAP + c*16, Ah + (size_t)(mb + row)*Kd + kc + c*8);
            cpa16(smb + al + row*GAP + c*16, Al + (size_t)(mb + row)*Kd + kc + c*8);
        }
        for (int it = t; it < 512; it += 256) {
            int row = it >> 4, c = it & 15;
            cpa16(smb + wh + row*GBP + c*16, Wh + (size_t)(kc + row)*OUTD + nbb + c*8);
            cpa16(smb + wl + row*GBP + c*16, Wl + (size_t)(kc + row)*OUTD + nbb + c*8);
        }
        cp_commit();
    };

    prefetch(0, 0);

    float acc[2][8][4];
#pragma unroll
    for (int mt = 0; mt < 2; mt++)
#pragma unroll
        for (int nt = 0; nt < 8; nt++)
#pragma unroll
            for (int v = 0; v < 4; v++) acc[mt][nt][v] = 0.f;

    for (int i = 0; i < NC; i++) {
        cp_wait0();
        __syncthreads();
        if (i + 1 < NC) prefetch(i + 1, (i + 1) & 1);
        const uint32_t ah = smb + ((i & 1) ? AH1 : AH0), al = smb + ((i & 1) ? AL1 : AL0);
        const uint32_t wh = smb + ((i & 1) ? WH1 : WH0), wl = smb + ((i & 1) ? WL1 : WL0);
#pragma unroll
        for (int ks = 0; ks < 2; ks++) {
            uint32_t afh[2][4], afl[2][4];
#pragma unroll
            for (int mt = 0; mt < 2; mt++) {
                uint32_t aoff = (wm + mt*16 + (lane & 15))*GAP + ks*32 + (lane >> 4)*16;
                ldsm4(afh[mt], ah + aoff);
                ldsm4(afl[mt], al + aoff);
            }
#pragma unroll
            for (int nt = 0; nt < 8; nt++) {
                uint32_t boff = (ks*16 + (lane & 15))*GBP + (wn + nt*8)*2;
                uint32_t bfh[2], bfl[2];
                ldsm2t(bfh, wh + boff);
                ldsm2t(bfl, wl + boff);
#pragma unroll
                for (int mt = 0; mt < 2; mt++) {
                    mma16816(acc[mt][nt], afh[mt], bfh);
                    mma16816(acc[mt][nt], afh[mt], bfl);
                    mma16816(acc[mt][nt], afl[mt], bfh);
                }
            }
        }
    }
#pragma unroll
    for (int mt = 0; mt < 2; mt++) {
#pragma unroll
        for (int nt = 0; nt < 8; nt++) {
            int m0 = mb + wm + mt*16 + (lane >> 2);
            int n0 = nbb + wn + nt*8 + 2*(lane & 3);
            float b0 = bias1[n0] + bias2[n0];
            float b1v = bias1[n0 + 1] + bias2[n0 + 1];
            float2 v0 = make_float2(acc[mt][nt][0] + b0, acc[mt][nt][1] + b1v);
            float2 v1 = make_float2(acc[mt][nt][2] + b0, acc[mt][nt][3] + b1v);
            *(float2*)(C + (size_t)m0 * OUTD + n0) = v0;
            *(float2*)(C + (size_t)(m0 + 8) * OUTD + n0) = v1;
        }
    }
}

// ---------------- launch ----------------
extern "C" void kernel_launch(void* const* d_in, const int* in_sizes, int n_in,
                              void* d_out, int out_size) {
    const float* x  = (const float*)d_in[0];
    const float* W1 = (const float*)d_in[2];
    const float* b1 = (const float*)d_in[3];
    const float* W2 = (const float*)d_in[4];
    const float* b2 = (const float*)d_in[5];
    const float* Ws = (const float*)d_in[6];
    const float* bs = (const float*)d_in[7];

    float* out  = (float*)d_out;
    float* esrc = out + (size_t)NTOT * OUTD;
    float* edst = esrc + NEDGE;
    int we = (out_size >= (int)((size_t)NTOT * OUTD + 2 * NEDGE)) ? 1 : 0;

    __half *xh, *xl, *axh, *axl, *h1h, *h1l, *ahh, *ahl;
    __half *w1h, *w1l, *w2h, *w2l, *wsh, *wsl;
    cudaGetSymbolAddress((void**)&xh, d_xh);
    cudaGetSymbolAddress((void**)&xl, d_xl);
    cudaGetSymbolAddress((void**)&axh, d_axh);
    cudaGetSymbolAddress((void**)&axl, d_axl);
    cudaGetSymbolAddress((void**)&h1h, d_h1h);
    cudaGetSymbolAddress((void**)&h1l, d_h1l);
    cudaGetSymbolAddress((void**)&ahh, d_ahh);
    cudaGetSymbolAddress((void**)&ahl, d_ahl);
    cudaGetSymbolAddress((void**)&w1h, d_w1h);
    cudaGetSymbolAddress((void**)&w1l, d_w1l);
    cudaGetSymbolAddress((void**)&w2h, d_w2h);
    cudaGetSymbolAddress((void**)&w2l, d_w2l);
    cudaGetSymbolAddress((void**)&wsh, d_wsh);
    cudaGetSymbolAddress((void**)&wsl, d_wsl);

    cudaFuncSetAttribute(k_knn, cudaFuncAttributeMaxDynamicSharedMemorySize, SMTOT);
    cudaFuncSetAttribute(k_gemm1, cudaFuncAttributeMaxDynamicSharedMemorySize, GSM);
    cudaFuncSetAttribute(k_gemm2, cudaFuncAttributeMaxDynamicSharedMemorySize, GSM);

    k_prep<<<NTOT / 8, 256>>>(x);
    k_splitw<<<(IND * OUTD + 255) / 256, 256>>>(W1, w1h, w1l, IND * OUTD);
    k_splitw<<<(OUTD * OUTD + 255) / 256, 256>>>(W2, w2h, w2l, OUTD * OUTD);
    k_splitw<<<(IND * OUTD + 255) / 256, 256>>>(Ws, wsh, wsl, IND * OUTD);

    k_knn<<<dim3(NN / 128, NB), 256, SMTOT>>>(xh, xl, esrc, edst, we);

    k_aggx<<<NTOT, 128>>>(x, axh, axl);
    k_gemm1<<<dim3(OUTD / 128, NTOT / 128), 256, GSM>>>(axh, axl, w1h, w1l, b1, h1h, h1l);
    k_aggh<<<NTOT, 256>>>(h1h, h1l, ahh, ahl);
    k_gemm2<<<dim3(OUTD / 128, NTOT / 128), 256, GSM>>>(ahh, ahl, w2h, w2l,
                                                        xh, xl, wsh, wsl,
                                                        b2, bs, out);
}

// round 9
// speedup vs baseline: 1.4981x; 1.0333x over previous
#include <cuda_runtime.h>
#include <cuda_fp16.h>
#include <stdint.h>

#define NB 16
#define NN 2048
#define NTOT (NB*NN)
#define KNB 16
#define IND 128
#define OUTD 256
#define NEDGE (NTOT*KNB)

// ---------------- scratch ----------------
__device__ float d_sqn[NTOT];
__device__ int   d_nbr[NTOT*KNB];
__device__ __half d_xh[(size_t)NTOT*IND];
__device__ __half d_xl[(size_t)NTOT*IND];
__device__ __half d_axh[(size_t)NTOT*IND];
__device__ __half d_axl[(size_t)NTOT*IND];
__device__ uint32_t d_h1p[(size_t)NTOT*OUTD];   // packed (h,l) per element
__device__ __half d_ahh[(size_t)NTOT*OUTD];
__device__ __half d_ahl[(size_t)NTOT*OUTD];
__device__ __half d_w1h[IND*OUTD],  d_w1l[IND*OUTD];
__device__ __half d_w2h[OUTD*OUTD], d_w2l[OUTD*OUTD];
__device__ __half d_wsh[IND*OUTD],  d_wsl[IND*OUTD];

// ---------------- helpers ----------------
__device__ __forceinline__ uint32_t smem_u32(const void* p) {
    uint32_t a;
    asm("{ .reg .u64 t; cvta.to.shared.u64 t, %1; cvt.u32.u64 %0, t; }" : "=r"(a) : "l"(p));
    return a;
}
__device__ __forceinline__ void cpa16(uint32_t dst, const void* src) {
    asm volatile("cp.async.cg.shared.global [%0], [%1], 16;" :: "r"(dst), "l"(src));
}
__device__ __forceinline__ void cp_commit() { asm volatile("cp.async.commit_group;"); }
__device__ __forceinline__ void cp_wait0()  { asm volatile("cp.async.wait_group 0;"); }
__device__ __forceinline__ void ldsm4(uint32_t* r, uint32_t a) {
    asm volatile("ldmatrix.sync.aligned.m8n8.x4.shared.b16 {%0,%1,%2,%3}, [%4];"
        : "=r"(r[0]), "=r"(r[1]), "=r"(r[2]), "=r"(r[3]) : "r"(a));
}
__device__ __forceinline__ void ldsm2t(uint32_t* r, uint32_t a) {
    asm volatile("ldmatrix.sync.aligned.m8n8.x2.trans.shared.b16 {%0,%1}, [%2];"
        : "=r"(r[0]), "=r"(r[1]) : "r"(a));
}
__device__ __forceinline__ void mma16816(float* c, const uint32_t* a, const uint32_t* b) {
    asm volatile("mma.sync.aligned.m16n8k16.row.col.f32.f16.f16.f32 "
        "{%0,%1,%2,%3}, {%4,%5,%6,%7}, {%8,%9}, {%0,%1,%2,%3};"
        : "+f"(c[0]), "+f"(c[1]), "+f"(c[2]), "+f"(c[3])
        : "r"(a[0]), "r"(a[1]), "r"(a[2]), "r"(a[3]), "r"(b[0]), "r"(b[1]));
}

// ---------------- prep: sqn + 2-way fp16 split of x (one pass) --------------
__global__ __launch_bounds__(256) void k_prep(const float* __restrict__ x) {
    const int row = blockIdx.x * 8 + (threadIdx.x >> 5);
    const int lane = threadIdx.x & 31;
    float4 v = *(const float4*)(x + (size_t)row * IND + lane * 4);
    float s = v.x*v.x + v.y*v.y + v.z*v.z + v.w*v.w;
#pragma unroll
    for (int o = 16; o > 0; o >>= 1) s += __shfl_xor_sync(0xffffffffu, s, o);
    if (lane == 0) d_sqn[row] = s;
    float f[4] = {v.x, v.y, v.z, v.w};
    __half h[4], l[4];
#pragma unroll
    for (int j = 0; j < 4; j++) {
        h[j] = __float2half_rn(f[j]);
        l[j] = __float2half_rn(f[j] - __half2float(h[j]));
    }
    const size_t o = (size_t)row * IND + lane * 4;
    *(uint2*)(d_xh + o) = *(uint2*)h;
    *(uint2*)(d_xl + o) = *(uint2*)l;
}

// ---------------- 2-way fp16 split (weights) ----------------
__global__ void k_splitw(const float* __restrict__ s, __half* __restrict__ hi,
                         __half* __restrict__ lo, int n) {
    int i = blockIdx.x * blockDim.x + threadIdx.x;
    if (i >= n) return;
    float f = s[i];
    __half h = __float2half_rn(f);
    hi[i] = h;
    lo[i] = __float2half_rn(f - __half2float(h));
}

// ---------------- kNN via fp16 mma.sync (2-way split, 3 passes) -------------
#define PB 272
#define TQB (128*PB)
#define TCB (64*PB)
#define SQ 0
#define SC (2*TQB)
#define SCSQ (SC + 4*TCB)
#define SMTOT (SCSQ + 2*64*4)
#define NCH (NN/64)

__device__ __forceinline__ void ins16(float* bd, int* bi, float key, int idx) {
    if (key < bd[15]) {
        bd[15] = key; bi[15] = idx;
#pragma unroll
        for (int j = 15; j > 0; j--) {
            if (bd[j] < bd[j-1]) {
                float tf = bd[j]; bd[j] = bd[j-1]; bd[j-1] = tf;
                int   ti = bi[j]; bi[j] = bi[j-1]; bi[j-1] = ti;
            }
        }
    }
}

__global__ __launch_bounds__(256)
void k_knn(const __half* __restrict__ xh, const __half* __restrict__ xl,
           float* __restrict__ esrc, float* __restrict__ edst, int we) {
    extern __shared__ char sm[];
    const uint32_t smb = smem_u32(sm);
    float* csq = (float*)(sm + SCSQ);
    const int t = threadIdx.x, w = t >> 5, lane = t & 31;
    const int b = blockIdx.y, qb = blockIdx.x * 128, gbase = b * NN;
    const float FINF = __int_as_float(0x7f800000);
    const __half* xs[2] = {xh, xl};

    for (int s = 0; s < 2; s++) {
        for (int it = t; it < 2048; it += 256) {
            int row = it >> 4, c = it & 15;
            cpa16(smb + SQ + s*TQB + row*PB + c*16,
                  xs[s] + ((size_t)(gbase + qb + row) << 7) + c*8);
        }
        for (int it = t; it < 1024; it += 256) {
            int row = it >> 4, c = it & 15;
            cpa16(smb + SC + s*TCB + row*PB + c*16,
                  xs[s] + ((size_t)(gbase + row) << 7) + c*8);
        }
    }
    if (t < 64) csq[t] = d_sqn[gbase + t];
    cp_commit();

    const int r0 = w * 16 + (lane >> 2);
    const int quarter = lane & 3;
    float bd0[16], bd1[16]; int bi0[16], bi1[16];
#pragma unroll
    for (int j = 0; j < 16; j++) { bd0[j] = FINF; bd1[j] = FINF; bi0[j] = 0; bi1[j] = 0; }

    for (int i = 0; i < NCH; i++) {
        cp_wait0();
        __syncthreads();
        const int buf = i & 1;
        if (i + 1 < NCH) {
            const int nb_ = (i + 1) & 1, cb2 = (i + 1) * 64;
            for (int s = 0; s < 2; s++)
                for (int it = t; it < 1024; it += 256) {
                    int row = it >> 4, c = it & 15;
                    cpa16(smb + SC + (nb_*2 + s)*TCB + row*PB + c*16,
                          xs[s] + ((size_t)(gbase + cb2 + row) << 7) + c*8);
                }
            if (t < 64) csq[nb_ * 64 + t] = d_sqn[gbase + cb2 + t];
            cp_commit();
        }
        const uint32_t chB = smb + SC + (buf*2) * TCB;
        const float* cs = csq + buf * 64;
        const int cb = i * 64;

        float acc[8][4];
#pragma unroll
        for (int nt = 0; nt < 8; nt++)
#pragma unroll
            for (int v = 0; v < 4; v++) acc[nt][v] = 0.f;

#pragma unroll 2
        for (int ks = 0; ks < 8; ks++) {
            uint32_t afh[4], afl[4];
            uint32_t abase = smb + SQ + (w*16 + (lane & 15))*PB + ks*32 + (lane >> 4)*16;
            ldsm4(afh, abase);
            ldsm4(afl, abase + TQB);
#pragma unroll
            for (int p = 0; p < 4; p++) {
                uint32_t bbase = chB + (p*16 + (lane >> 4)*8 + (lane & 7))*PB
                               + ks*32 + ((lane >> 3) & 1)*16;
                uint32_t bh[4], bl[4];
                ldsm4(bh, bbase);
                ldsm4(bl, bbase + TCB);
                mma16816(acc[2*p],     afh, bh);
                mma16816(acc[2*p],     afh, bl);
                mma16816(acc[2*p],     afl, bh);
                mma16816(acc[2*p + 1], afh, bh + 2);
                mma16816(acc[2*p + 1], afh, bl + 2);
                mma16816(acc[2*p + 1], afl, bh + 2);
            }
        }
#pragma unroll
        for (int nt = 0; nt < 8; nt++) {
            int cl = nt*8 + 2*quarter;
            float cq0 = cs[cl], cq1 = cs[cl + 1];
            float k00 = fmaf(-2.f, acc[nt][0], cq0);
            float k01 = fmaf(-2.f, acc[nt][1], cq1);
            float k10 = fmaf(-2.f, acc[nt][2], cq0);
            float k11 = fmaf(-2.f, acc[nt][3], cq1);
            int ci = cb + cl;
            if (qb + r0 == ci)         k00 = FINF;
            if (qb + r0 == ci + 1)     k01 = FINF;
            if (qb + r0 + 8 == ci)     k10 = FINF;
            if (qb + r0 + 8 == ci + 1) k11 = FINF;
            ins16(bd0, bi0, k00, ci);
            ins16(bd0, bi0, k01, ci + 1);
            ins16(bd1, bi1, k10, ci);
            ins16(bd1, bi1, k11, ci + 1);
        }
    }
    __syncthreads();

    float* dk = (float*)(sm + SC);
    int*   di = (int*)(sm + SC + 32768);
#pragma unroll
    for (int j = 0; j < 16; j++) {
        dk[(r0*4 + quarter)*16 + j] = bd0[j];
        di[(r0*4 + quarter)*16 + j] = bi0[j];
        dk[((r0 + 8)*4 + quarter)*16 + j] = bd1[j];
        di[((r0 + 8)*4 + quarter)*16 + j] = bi1[j];
    }
    __syncthreads();

    if (t < 128) {
        int p[4] = {0, 0, 0, 0};
        int qg = gbase + qb + t;
#pragma unroll 1
        for (int k = 0; k < 16; k++) {
            float best = FINF; int bidx = 0x7fffffff; int bl = 0;
#pragma unroll
            for (int j = 0; j < 4; j++) {
                bool ok = p[j] < 16;
                float kv = ok ? dk[(t*4 + j)*16 + p[j]] : FINF;
                int   iv = ok ? di[(t*4 + j)*16 + p[j]] : 0x7fffffff;
                if (kv < best || (kv == best && iv < bidx)) { best = kv; bidx = iv; bl = j; }
            }
            p[bl]++;
            int sg = gbase + bidx;
            size_t e = (size_t)qg * KNB + k;
            d_nbr[e] = sg;
            if (we) { esrc[e] = (float)sg; edst[e] = (float)qg; }
        }
    }
}

// ---------------- agg(x): 128-dim fp32 gather, 2 nodes/block ---------------
__global__ __launch_bounds__(256) void k_aggx(const float* __restrict__ x,
                                              __half* __restrict__ oh,
                                              __half* __restrict__ ol) {
    const int node = blockIdx.x * 2 + (threadIdx.x >> 7);
    const int t = threadIdx.x & 127;
    __shared__ int nb_s[2][KNB];
    if (t < KNB) nb_s[threadIdx.x >> 7][t] = d_nbr[(size_t)node * KNB + t];
    __syncthreads();
    const int* nbp = nb_s[threadIdx.x >> 7];
    const float norm = 1.0f / 17.0f;
    float acc = 0.f;
#pragma unroll
    for (int k = 0; k < KNB; k++) acc += x[(size_t)nbp[k] * IND + t] * norm;
    acc += x[(size_t)node * IND + t] * norm;
    __half h = __float2half_rn(acc);
    oh[(size_t)node * IND + t] = h;
    ol[(size_t)node * IND + t] = __float2half_rn(acc - __half2float(h));
}

// ---------------- agg(h1): 256-dim packed gather -> fp16 split pair --------
__global__ __launch_bounds__(256) void k_aggh(const uint32_t* __restrict__ gp,
                                              __half* __restrict__ oh,
                                              __half* __restrict__ ol) {
    const int node = blockIdx.x;
    const int t = threadIdx.x;
    __shared__ int nb_s[KNB];
    if (t < KNB) nb_s[t] = d_nbr[(size_t)node * KNB + t];
    __syncthreads();
    const float norm = 1.0f / 17.0f;
    float acc = 0.f;
#pragma unroll
    for (int k = 0; k < KNB; k++) {
        uint32_t p = gp[(size_t)nb_s[k] * OUTD + t];
        acc += (__half2float(__ushort_as_half((unsigned short)(p & 0xffff)))
              + __half2float(__ushort_as_half((unsigned short)(p >> 16)))) * norm;
    }
    {
        uint32_t p = gp[(size_t)node * OUTD + t];
        acc += (__half2float(__ushort_as_half((unsigned short)(p & 0xffff)))
              + __half2float(__ushort_as_half((unsigned short)(p >> 16)))) * norm;
    }
    __half h = __float2half_rn(acc);
    oh[(size_t)node * OUTD + t] = h;
    ol[(size_t)node * OUTD + t] = __float2half_rn(acc - __half2float(h));
}

// ---------------- GEMM smem layout ----------------
#define GAP 80
#define GBP 272
#define AH0 0
#define AL0 10240
#define AH1 20480
#define AL1 30720
#define WH0 40960
#define WL0 49664
#define WH1 58368
#define WL1 67072
#define GSM 75776

// ---------------- GEMM1: h1 = relu(ax@W1 + b1) -> packed (h,l) --------------
__global__ __launch_bounds__(256)
void k_gemm1(const __half* __restrict__ Ahi, const __half* __restrict__ Alo,
             const __half* __restrict__ Whi, const __half* __restrict__ Wlo,
             const float* __restrict__ bias, uint32_t* __restrict__ Cp) {
    extern __shared__ char sm[];
    const uint32_t smb = smem_u32(sm);
    const int t = threadIdx.x, w = t >> 5, lane = t & 31;
    const int nbb = blockIdx.x * 128, mb = blockIdx.y * 128;
    const int wm = (w >> 1) * 32, wn = (w & 1) * 64;
    const int Kd = IND, nchunk = IND / 32;

    for (int it = t; it < 512; it += 256) {
        int row = it >> 2, c = it & 3;
        cpa16(smb + AH0 + row*GAP + c*16, Ahi + (size_t)(mb + row)*Kd + c*8);
        cpa16(smb + AL0 + row*GAP + c*16, Alo + (size_t)(mb + row)*Kd + c*8);
    }
    for (int it = t; it < 512; it += 256) {
        int row = it >> 4, c = it & 15;
        cpa16(smb + WH0 + row*GBP + c*16, Whi + (size_t)row*OUTD + nbb + c*8);
        cpa16(smb + WL0 + row*GBP + c*16, Wlo + (size_t)row*OUTD + nbb + c*8);
    }
    cp_commit();

    float acc[2][8][4];
#pragma unroll
    for (int mt = 0; mt < 2; mt++)
#pragma unroll
        for (int nt = 0; nt < 8; nt++)
#pragma unroll
            for (int v = 0; v < 4; v++) acc[mt][nt][v] = 0.f;

    for (int i = 0; i < nchunk; i++) {
        cp_wait0();
        __syncthreads();
        if (i + 1 < nchunk) {
            uint32_t ah = ((i + 1) & 1) ? AH1 : AH0, al = ((i + 1) & 1) ? AL1 : AL0;
            uint32_t wh = ((i + 1) & 1) ? WH1 : WH0, wl = ((i + 1) & 1) ? WL1 : WL0;
            int kc = (i + 1) * 32;
            for (int it = t; it < 512; it += 256) {
                int row = it >> 2, c = it & 3;
                cpa16(smb + ah + row*GAP + c*16, Ahi + (size_t)(mb + row)*Kd + kc + c*8);
                cpa16(smb + al + row*GAP + c*16, Alo + (size_t)(mb + row)*Kd + kc + c*8);
            }
            for (int it = t; it < 512; it += 256) {
                int row = it >> 4, c = it & 15;
                cpa16(smb + wh + row*GBP + c*16, Whi + (size_t)(kc + row)*OUTD + nbb + c*8);
                cpa16(smb + wl + row*GBP + c*16, Wlo + (size_t)(kc + row)*OUTD + nbb + c*8);
            }
            cp_commit();
        }
        const uint32_t ah = smb + ((i & 1) ? AH1 : AH0), al = smb + ((i & 1) ? AL1 : AL0);
        const uint32_t wh = smb + ((i & 1) ? WH1 : WH0), wl = smb + ((i & 1) ? WL1 : WL0);
#pragma unroll
        for (int ks = 0; ks < 2; ks++) {
            uint32_t afh[2][4], afl[2][4];
#pragma unroll
            for (int mt = 0; mt < 2; mt++) {
                uint32_t aoff = (wm + mt*16 + (lane & 15))*GAP + ks*32 + (lane >> 4)*16;
                ldsm4(afh[mt], ah + aoff);
                ldsm4(afl[mt], al + aoff);
            }
#pragma unroll
            for (int nt = 0; nt < 8; nt++) {
                uint32_t boff = (ks*16 + (lane & 15))*GBP + (wn + nt*8)*2;
                uint32_t bfh[2], bfl[2];
                ldsm2t(bfh, wh + boff);
                ldsm2t(bfl, wl + boff);
#pragma unroll
                for (int mt = 0; mt < 2; mt++) {
                    mma16816(acc[mt][nt], afh[mt], bfh);
                    mma16816(acc[mt][nt], afh[mt], bfl);
                    mma16816(acc[mt][nt], afl[mt], bfh);
                }
            }
        }
    }
#pragma unroll
    for (int mt = 0; mt < 2; mt++) {
#pragma unroll
        for (int nt = 0; nt < 8; nt++) {
            int m0 = mb + wm + mt*16 + (lane >> 2);
            int n0 = nbb + wn + nt*8 + 2*(lane & 3);
            float b0 = bias[n0], b1v = bias[n0 + 1];
#pragma unroll
            for (int rr = 0; rr < 2; rr++) {
                int m = m0 + rr * 8;
                float v0 = fmaxf(acc[mt][nt][rr*2 + 0] + b0, 0.f);
                float v1 = fmaxf(acc[mt][nt][rr*2 + 1] + b1v, 0.f);
                __half h0 = __float2half_rn(v0), h1 = __float2half_rn(v1);
                __half l0 = __float2half_rn(v0 - __half2float(h0));
                __half l1 = __float2half_rn(v1 - __half2float(h1));
                uint2 pk;
                pk.x = (uint32_t)__half_as_ushort(h0) | ((uint32_t)__half_as_ushort(l0) << 16);
                pk.y = (uint32_t)__half_as_ushort(h1) | ((uint32_t)__half_as_ushort(l1) << 16);
                *(uint2*)(Cp + (size_t)m * OUTD + n0) = pk;
            }
        }
    }
}

// ---------------- GEMM2: out = ah@W2 + x@Ws + (b2+bs) -----------------------
__global__ __launch_bounds__(256)
void k_gemm2(const __half* __restrict__ A1h, const __half* __restrict__ A1l,
             const __half* __restrict__ W1h_, const __half* __restrict__ W1l_,
             const __half* __restrict__ A2h, const __half* __restrict__ A2l,
             const __half* __restrict__ W2h_, const __half* __restrict__ W2l_,
             const float* __restrict__ bias1, const float* __restrict__ bias2,
             float* __restrict__ C) {
    extern __shared__ char sm[];
    const uint32_t smb = smem_u32(sm);
    const int t = threadIdx.x, w = t >> 5, lane = t & 31;
    const int nbb = blockIdx.x * 128, mb = blockIdx.y * 128;
    const int wm = (w >> 1) * 32, wn = (w & 1) * 64;
    const int NC1 = OUTD / 32;
    const int NC = NC1 + IND / 32;

    auto prefetch = [&](int j, int pb) {
        uint32_t ah = pb ? AH1 : AH0, al = pb ? AL1 : AL0;
        uint32_t wh = pb ? WH1 : WH0, wl = pb ? WL1 : WL0;
        const __half *Ah, *Al, *Wh, *Wl;
        int Kd, kc;
        if (j < NC1) { Ah = A1h; Al = A1l; Wh = W1h_; Wl = W1l_; Kd = OUTD; kc = j * 32; }
        else         { Ah = A2h; Al = A2l; Wh = W2h_; Wl = W2l_; Kd = IND;  kc = (j - NC1) * 32; }
        for (int it = t; it < 512; it += 256) {
            int row = it >> 2, c = it & 3;
            cpa16(smb + ah + row*GAP + c*16, Ah + (size_t)(mb + row)*Kd + kc + c*8);
            cpa16(smb + al + row*GAP + c*16, Al + (size_t)(mb + row)*Kd + kc + c*8);
        }
        for (int it = t; it < 512; it += 256) {
            int row = it >> 4, c = it & 15;
            cpa16(smb + wh + row*GBP + c*16, Wh + (size_t)(kc + row)*OUTD + nbb + c*8);
            cpa16(smb + wl + row*GBP + c*16, Wl + (size_t)(kc + row)*OUTD + nbb + c*8);
        }
        cp_commit();
    };

    prefetch(0, 0);

    float acc[2][8][4];
#pragma unroll
    for (int mt = 0; mt < 2; mt++)
#pragma unroll
        for (int nt = 0; nt < 8; nt++)
#pragma unroll
            for (int v = 0; v < 4; v++) acc[mt][nt][v] = 0.f;

    for (int i = 0; i < NC; i++) {
        cp_wait0();
        __syncthreads();
        if (i + 1 < NC) prefetch(i + 1, (i + 1) & 1);
        const uint32_t ah = smb + ((i & 1) ? AH1 : AH0), al = smb + ((i & 1) ? AL1 : AL0);
        const uint32_t wh = smb + ((i & 1) ? WH1 : WH0), wl = smb + ((i & 1) ? WL1 : WL0);
#pragma unroll
        for (int ks = 0; ks < 2; ks++) {
            uint32_t afh[2][4], afl[2][4];
#pragma unroll
            for (int mt = 0; mt < 2; mt++) {
                uint32_t aoff = (wm + mt*16 + (lane & 15))*GAP + ks*32 + (lane >> 4)*16;
                ldsm4(afh[mt], ah + aoff);
                ldsm4(afl[mt], al + aoff);
            }
#pragma unroll
            for (int nt = 0; nt < 8; nt++) {
                uint32_t boff = (ks*16 + (lane & 15))*GBP + (wn + nt*8)*2;
                uint32_t bfh[2], bfl[2];
                ldsm2t(bfh, wh + boff);
                ldsm2t(bfl, wl + boff);
#pragma unroll
                for (int mt = 0; mt < 2; mt++) {
                    mma16816(acc[mt][nt], afh[mt], bfh);
                    mma16816(acc[mt][nt], afh[mt], bfl);
                    mma16816(acc[mt][nt], afl[mt], bfh);
                }
            }
        }
    }
#pragma unroll
    for (int mt = 0; mt < 2; mt++) {
#pragma unroll
        for (int nt = 0; nt < 8; nt++) {
            int m0 = mb + wm + mt*16 + (lane >> 2);
            int n0 = nbb + wn + nt*8 + 2*(lane & 3);
            float b0 = bias1[n0] + bias2[n0];
            float b1v = bias1[n0 + 1] + bias2[n0 + 1];
            float2 v0 = make_float2(acc[mt][nt][0] + b0, acc[mt][nt][1] + b1v);
            float2 v1 = make_float2(acc[mt][nt][2] + b0, acc[mt][nt][3] + b1v);
            *(float2*)(C + (size_t)m0 * OUTD + n0) = v0;
            *(float2*)(C + (size_t)(m0 + 8) * OUTD + n0) = v1;
        }
    }
}

// ---------------- launch ----------------
extern "C" void kernel_launch(void* const* d_in, const int* in_sizes, int n_in,
                              void* d_out, int out_size) {
    const float* x  = (const float*)d_in[0];
    const float* W1 = (const float*)d_in[2];
    const float* b1 = (const float*)d_in[3];
    const float* W2 = (const float*)d_in[4];
    const float* b2 = (const float*)d_in[5];
    const float* Ws = (const float*)d_in[6];
    const float* bs = (const float*)d_in[7];

    float* out  = (float*)d_out;
    float* esrc = out + (size_t)NTOT * OUTD;
    float* edst = esrc + NEDGE;
    int we = (out_size >= (int)((size_t)NTOT * OUTD + 2 * NEDGE)) ? 1 : 0;

    __half *xh, *xl, *axh, *axl, *ahh, *ahl;
    uint32_t *h1p;
    __half *w1h, *w1l, *w2h, *w2l, *wsh, *wsl;
    cudaGetSymbolAddress((void**)&xh, d_xh);
    cudaGetSymbolAddress((void**)&xl, d_xl);
    cudaGetSymbolAddress((void**)&axh, d_axh);
    cudaGetSymbolAddress((void**)&axl, d_axl);
    cudaGetSymbolAddress((void**)&h1p, d_h1p);
    cudaGetSymbolAddress((void**)&ahh, d_ahh);
    cudaGetSymbolAddress((void**)&ahl, d_ahl);
    cudaGetSymbolAddress((void**)&w1h, d_w1h);
    cudaGetSymbolAddress((void**)&w1l, d_w1l);
    cudaGetSymbolAddress((void**)&w2h, d_w2h);
    cudaGetSymbolAddress((void**)&w2l, d_w2l);
    cudaGetSymbolAddress((void**)&wsh, d_wsh);
    cudaGetSymbolAddress((void**)&wsl, d_wsl);

    cudaFuncSetAttribute(k_knn, cudaFuncAttributeMaxDynamicSharedMemorySize, SMTOT);
    cudaFuncSetAttribute(k_gemm1, cudaFuncAttributeMaxDynamicSharedMemorySize, GSM);
    cudaFuncSetAttribute(k_gemm2, cudaFuncAttributeMaxDynamicSharedMemorySize, GSM);

    // launch order: k_knn at index 3 (ncu captures launch #3)
    k_prep<<<NTOT / 8, 256>>>(x);                                      // 0
    k_splitw<<<(IND * OUTD + 255) / 256, 256>>>(W1, w1h, w1l, IND * OUTD);   // 1
    k_splitw<<<(IND * OUTD + 255) / 256, 256>>>(Ws, wsh, wsl, IND * OUTD);   // 2
    k_knn<<<dim3(NN / 128, NB), 256, SMTOT>>>(xh, xl, esrc, edst, we); // 3
    k_splitw<<<(OUTD * OUTD + 255) / 256, 256>>>(W2, w2h, w2l, OUTD * OUTD); // 4
    k_aggx<<<NTOT / 2, 256>>>(x, axh, axl);                            // 5
    k_gemm1<<<dim3(OUTD / 128, NTOT / 128), 256, GSM>>>(axh, axl, w1h, w1l, b1, h1p); // 6
    k_aggh<<<NTOT, 256>>>(h1p, ahh, ahl);                              // 7
    k_gemm2<<<dim3(OUTD / 128, NTOT / 128), 256, GSM>>>(ahh, ahl, w2h, w2l,
                                                        xh, xl, wsh, wsl,
                                                        b2, bs, out);  // 8
}

// round 10
// speedup vs baseline: 2.0011x; 1.3357x over previous
#include <cuda_runtime.h>
#include <cuda_fp16.h>
#include <stdint.h>

#define NB 16
#define NN 2048
#define NTOT (NB*NN)
#define KNB 16
#define IND 128
#define OUTD 256
#define NEDGE (NTOT*KNB)

// ---------------- scratch ----------------
__device__ float d_sqn[NTOT];
__device__ int   d_nbr[NTOT*KNB];
__device__ __half d_xh[(size_t)NTOT*IND];
__device__ __half d_xl[(size_t)NTOT*IND];
__device__ __half d_axh[(size_t)NTOT*IND];
__device__ __half d_axl[(size_t)NTOT*IND];
__device__ uint32_t d_h1p[(size_t)NTOT*OUTD];
__device__ __half d_ahh[(size_t)NTOT*OUTD];
__device__ __half d_ahl[(size_t)NTOT*OUTD];
__device__ __half d_w1h[IND*OUTD],  d_w1l[IND*OUTD];
__device__ __half d_w2h[OUTD*OUTD], d_w2l[OUTD*OUTD];
__device__ __half d_wsh[IND*OUTD],  d_wsl[IND*OUTD];

// ---------------- helpers ----------------
__device__ __forceinline__ uint32_t smem_u32(const void* p) {
    uint32_t a;
    asm("{ .reg .u64 t; cvta.to.shared.u64 t, %1; cvt.u32.u64 %0, t; }" : "=r"(a) : "l"(p));
    return a;
}
__device__ __forceinline__ void cpa16(uint32_t dst, const void* src) {
    asm volatile("cp.async.cg.shared.global [%0], [%1], 16;" :: "r"(dst), "l"(src));
}
__device__ __forceinline__ void cp_commit() { asm volatile("cp.async.commit_group;"); }
__device__ __forceinline__ void cp_wait0()  { asm volatile("cp.async.wait_group 0;"); }
__device__ __forceinline__ void ldsm4(uint32_t* r, uint32_t a) {
    asm volatile("ldmatrix.sync.aligned.m8n8.x4.shared.b16 {%0,%1,%2,%3}, [%4];"
        : "=r"(r[0]), "=r"(r[1]), "=r"(r[2]), "=r"(r[3]) : "r"(a));
}
__device__ __forceinline__ void ldsm2t(uint32_t* r, uint32_t a) {
    asm volatile("ldmatrix.sync.aligned.m8n8.x2.trans.shared.b16 {%0,%1}, [%2];"
        : "=r"(r[0]), "=r"(r[1]) : "r"(a));
}
__device__ __forceinline__ void mma16816(float* c, const uint32_t* a, const uint32_t* b) {
    asm volatile("mma.sync.aligned.m16n8k16.row.col.f32.f16.f16.f32 "
        "{%0,%1,%2,%3}, {%4,%5,%6,%7}, {%8,%9}, {%0,%1,%2,%3};"
        : "+f"(c[0]), "+f"(c[1]), "+f"(c[2]), "+f"(c[3])
        : "r"(a[0]), "r"(a[1]), "r"(a[2]), "r"(a[3]), "r"(b[0]), "r"(b[1]));
}

// ---------------- prep: sqn + 2-way fp16 split of x ----------------
__global__ __launch_bounds__(256) void k_prep(const float* __restrict__ x) {
    const int row = blockIdx.x * 8 + (threadIdx.x >> 5);
    const int lane = threadIdx.x & 31;
    float4 v = *(const float4*)(x + (size_t)row * IND + lane * 4);
    float s = v.x*v.x + v.y*v.y + v.z*v.z + v.w*v.w;
#pragma unroll
    for (int o = 16; o > 0; o >>= 1) s += __shfl_xor_sync(0xffffffffu, s, o);
    if (lane == 0) d_sqn[row] = s;
    float f[4] = {v.x, v.y, v.z, v.w};
    __half h[4], l[4];
#pragma unroll
    for (int j = 0; j < 4; j++) {
        h[j] = __float2half_rn(f[j]);
        l[j] = __float2half_rn(f[j] - __half2float(h[j]));
    }
    const size_t o = (size_t)row * IND + lane * 4;
    *(uint2*)(d_xh + o) = *(uint2*)h;
    *(uint2*)(d_xl + o) = *(uint2*)l;
}

__global__ void k_splitw(const float* __restrict__ s, __half* __restrict__ hi,
                         __half* __restrict__ lo, int n) {
    int i = blockIdx.x * blockDim.x + threadIdx.x;
    if (i >= n) return;
    float f = s[i];
    __half h = __float2half_rn(f);
    hi[i] = h;
    lo[i] = __float2half_rn(f - __half2float(h));
}

// ---------------- kNN: fp16 HMMA, chunk=32, 2 CTAs/SM -----------------------
#define PB 272
#define TQB (128*PB)              // 34816 per query split tile
#define TCB (32*PB)               // 8704 per cand split tile
#define SQ 0
#define SC (2*TQB)                // 69632
#define SCSQ (SC + 4*TCB)         // 69632 + 34816 = 104448
#define SMTOT (SCSQ + 2*32*4)     // 104704 (~102.3 KB) -> 2 CTAs/SM
#define NCH (NN/32)               // 64 chunks

// packed 16-bit index helpers (constant j after unroll -> folds)
__device__ __forceinline__ uint32_t get16(const uint32_t* a, int j) {
    return (a[j >> 1] >> ((j & 1) * 16)) & 0xffffu;
}
__device__ __forceinline__ void set16(uint32_t* a, int j, uint32_t v) {
    const int sh = (j & 1) * 16;
    a[j >> 1] = (a[j >> 1] & ~(0xffffu << sh)) | (v << sh);
}
__device__ __forceinline__ void ins16p(float* bd, uint32_t* bip, float key, uint32_t idx) {
    if (key < bd[15]) {
        bd[15] = key; set16(bip, 15, idx);
#pragma unroll
        for (int j = 15; j > 0; j--) {
            if (bd[j] < bd[j-1]) {
                float tf = bd[j]; bd[j] = bd[j-1]; bd[j-1] = tf;
                uint32_t a = get16(bip, j), b = get16(bip, j-1);
                set16(bip, j, b); set16(bip, j-1, a);
            }
        }
    }
}

__global__ __launch_bounds__(256, 2)
void k_knn(const __half* __restrict__ xh, const __half* __restrict__ xl,
           float* __restrict__ esrc, float* __restrict__ edst, int we) {
    extern __shared__ char sm[];
    const uint32_t smb = smem_u32(sm);
    float* csq = (float*)(sm + SCSQ);
    const int t = threadIdx.x, w = t >> 5, lane = t & 31;
    const int b = blockIdx.y, qb = blockIdx.x * 128, gbase = b * NN;
    const float FINF = __int_as_float(0x7f800000);
    const __half* xs[2] = {xh, xl};

    // prologue: 2 query split tiles + candidate chunk 0
    for (int s = 0; s < 2; s++) {
        for (int it = t; it < 2048; it += 256) {
            int row = it >> 4, c = it & 15;
            cpa16(smb + SQ + s*TQB + row*PB + c*16,
                  xs[s] + ((size_t)(gbase + qb + row) << 7) + c*8);
        }
        for (int it = t; it < 512; it += 256) {
            int row = it >> 4, c = it & 15;
            cpa16(smb + SC + s*TCB + row*PB + c*16,
                  xs[s] + ((size_t)(gbase + row) << 7) + c*8);
        }
    }
    if (t < 32) csq[t] = d_sqn[gbase + t];
    cp_commit();

    const int r0 = w * 16 + (lane >> 2);
    const int quarter = lane & 3;
    float bd0[16], bd1[16];
    uint32_t bip0[8], bip1[8];
#pragma unroll
    for (int j = 0; j < 16; j++) { bd0[j] = FINF; bd1[j] = FINF; }
#pragma unroll
    for (int j = 0; j < 8; j++) { bip0[j] = 0; bip1[j] = 0; }

    for (int i = 0; i < NCH; i++) {
        cp_wait0();
        __syncthreads();
        const int buf = i & 1;
        if (i + 1 < NCH) {
            const int nb_ = (i + 1) & 1, cb2 = (i + 1) * 32;
            for (int s = 0; s < 2; s++)
                for (int it = t; it < 512; it += 256) {
                    int row = it >> 4, c = it & 15;
                    cpa16(smb + SC + (nb_*2 + s)*TCB + row*PB + c*16,
                          xs[s] + ((size_t)(gbase + cb2 + row) << 7) + c*8);
                }
            if (t < 32) csq[nb_ * 32 + t] = d_sqn[gbase + cb2 + t];
            cp_commit();
        }
        const uint32_t chB = smb + SC + (buf*2) * TCB;
        const float* cs = csq + buf * 32;
        const int cb = i * 32;

        float acc[4][4];
#pragma unroll
        for (int nt = 0; nt < 4; nt++)
#pragma unroll
            for (int v = 0; v < 4; v++) acc[nt][v] = 0.f;

#pragma unroll 2
        for (int ks = 0; ks < 8; ks++) {
            uint32_t afh[4], afl[4];
            uint32_t abase = smb + SQ + (w*16 + (lane & 15))*PB + ks*32 + (lane >> 4)*16;
            ldsm4(afh, abase);
            ldsm4(afl, abase + TQB);
#pragma unroll
            for (int p = 0; p < 2; p++) {
                uint32_t bbase = chB + (p*16 + (lane >> 4)*8 + (lane & 7))*PB
                               + ks*32 + ((lane >> 3) & 1)*16;
                uint32_t bh[4], bl[4];
                ldsm4(bh, bbase);
                ldsm4(bl, bbase + TCB);
                mma16816(acc[2*p],     afh, bh);
                mma16816(acc[2*p],     afh, bl);
                mma16816(acc[2*p],     afl, bh);
                mma16816(acc[2*p + 1], afh, bh + 2);
                mma16816(acc[2*p + 1], afh, bl + 2);
                mma16816(acc[2*p + 1], afl, bh + 2);
            }
        }

        // selection; self-exclusion only on chunks intersecting query range
        const bool diag = (cb >= qb) && (cb < qb + 128);
        if (diag) {
#pragma unroll
            for (int nt = 0; nt < 4; nt++) {
                int cl = nt*8 + 2*quarter;
                float cq0 = cs[cl], cq1 = cs[cl + 1];
                float k00 = fmaf(-2.f, acc[nt][0], cq0);
                float k01 = fmaf(-2.f, acc[nt][1], cq1);
                float k10 = fmaf(-2.f, acc[nt][2], cq0);
                float k11 = fmaf(-2.f, acc[nt][3], cq1);
                int ci = cb + cl;
                if (qb + r0 == ci)         k00 = FINF;
                if (qb + r0 == ci + 1)     k01 = FINF;
                if (qb + r0 + 8 == ci)     k10 = FINF;
                if (qb + r0 + 8 == ci + 1) k11 = FINF;
                ins16p(bd0, bip0, k00, (uint32_t)ci);
                ins16p(bd0, bip0, k01, (uint32_t)(ci + 1));
                ins16p(bd1, bip1, k10, (uint32_t)ci);
                ins16p(bd1, bip1, k11, (uint32_t)(ci + 1));
            }
        } else {
#pragma unroll
            for (int nt = 0; nt < 4; nt++) {
                int cl = nt*8 + 2*quarter;
                float cq0 = cs[cl], cq1 = cs[cl + 1];
                float k00 = fmaf(-2.f, acc[nt][0], cq0);
                float k01 = fmaf(-2.f, acc[nt][1], cq1);
                float k10 = fmaf(-2.f, acc[nt][2], cq0);
                float k11 = fmaf(-2.f, acc[nt][3], cq1);
                int ci = cb + cl;
                ins16p(bd0, bip0, k00, (uint32_t)ci);
                ins16p(bd0, bip0, k01, (uint32_t)(ci + 1));
                ins16p(bd1, bip1, k10, (uint32_t)ci);
                ins16p(bd1, bip1, k11, (uint32_t)(ci + 1));
            }
        }
    }
    __syncthreads();

    // dump lists into the (now dead) query tile area
    float* dk = (float*)(sm + SQ);
    int*   di = (int*)(sm + SQ + 32768);
#pragma unroll
    for (int j = 0; j < 16; j++) {
        dk[(r0*4 + quarter)*16 + j] = bd0[j];
        di[(r0*4 + quarter)*16 + j] = (int)get16(bip0, j);
        dk[((r0 + 8)*4 + quarter)*16 + j] = bd1[j];
        di[((r0 + 8)*4 + quarter)*16 + j] = (int)get16(bip1, j);
    }
    __syncthreads();

    // 4-way merge per query (lexicographic (key, idx) == top_k tie-break)
    if (t < 128) {
        int p[4] = {0, 0, 0, 0};
        int qg = gbase + qb + t;
#pragma unroll 1
        for (int k = 0; k < 16; k++) {
            float best = FINF; int bidx = 0x7fffffff; int bl = 0;
#pragma unroll
            for (int j = 0; j < 4; j++) {
                bool ok = p[j] < 16;
                float kv = ok ? dk[(t*4 + j)*16 + p[j]] : FINF;
                int   iv = ok ? di[(t*4 + j)*16 + p[j]] : 0x7fffffff;
                if (kv < best || (kv == best && iv < bidx)) { best = kv; bidx = iv; bl = j; }
            }
            p[bl]++;
            int sg = gbase + bidx;
            size_t e = (size_t)qg * KNB + k;
            d_nbr[e] = sg;
            if (we) { esrc[e] = (float)sg; edst[e] = (float)qg; }
        }
    }
}

// ---------------- agg(x): 128-dim fp32 gather, 2 nodes/block ---------------
__global__ __launch_bounds__(256) void k_aggx(const float* __restrict__ x,
                                              __half* __restrict__ oh,
                                              __half* __restrict__ ol) {
    const int node = blockIdx.x * 2 + (threadIdx.x >> 7);
    const int t = threadIdx.x & 127;
    __shared__ int nb_s[2][KNB];
    if (t < KNB) nb_s[threadIdx.x >> 7][t] = d_nbr[(size_t)node * KNB + t];
    __syncthreads();
    const int* nbp = nb_s[threadIdx.x >> 7];
    const float norm = 1.0f / 17.0f;
    float acc = 0.f;
#pragma unroll
    for (int k = 0; k < KNB; k++) acc += x[(size_t)nbp[k] * IND + t] * norm;
    acc += x[(size_t)node * IND + t] * norm;
    __half h = __float2half_rn(acc);
    oh[(size_t)node * IND + t] = h;
    ol[(size_t)node * IND + t] = __float2half_rn(acc - __half2float(h));
}

// ---------------- agg(h1): 256-dim packed gather ----------------------------
__global__ __launch_bounds__(256) void k_aggh(const uint32_t* __restrict__ gp,
                                              __half* __restrict__ oh,
                                              __half* __restrict__ ol) {
    const int node = blockIdx.x;
    const int t = threadIdx.x;
    __shared__ int nb_s[KNB];
    if (t < KNB) nb_s[t] = d_nbr[(size_t)node * KNB + t];
    __syncthreads();
    const float norm = 1.0f / 17.0f;
    float acc = 0.f;
#pragma unroll
    for (int k = 0; k < KNB; k++) {
        uint32_t p = gp[(size_t)nb_s[k] * OUTD + t];
        acc += (__half2float(__ushort_as_half((unsigned short)(p & 0xffff)))
              + __half2float(__ushort_as_half((unsigned short)(p >> 16)))) * norm;
    }
    {
        uint32_t p = gp[(size_t)node * OUTD + t];
        acc += (__half2float(__ushort_as_half((unsigned short)(p & 0xffff)))
              + __half2float(__ushort_as_half((unsigned short)(p >> 16)))) * norm;
    }
    __half h = __float2half_rn(acc);
    oh[(size_t)node * OUTD + t] = h;
    ol[(size_t)node * OUTD + t] = __float2half_rn(acc - __half2float(h));
}

// ---------------- GEMM smem layout ----------------
#define GAP 80
#define GBP 272
#define AH0 0
#define AL0 10240
#define AH1 20480
#define AL1 30720
#define WH0 40960
#define WL0 49664
#define WH1 58368
#define WL1 67072
#define GSM 75776

// ---------------- GEMM1: h1 = relu(ax@W1 + b1) -> packed (h,l) --------------
__global__ __launch_bounds__(256)
void k_gemm1(const __half* __restrict__ Ahi, const __half* __restrict__ Alo,
             const __half* __restrict__ Whi, const __half* __restrict__ Wlo,
             const float* __restrict__ bias, uint32_t* __restrict__ Cp) {
    extern __shared__ char sm[];
    const uint32_t smb = smem_u32(sm);
    const int t = threadIdx.x, w = t >> 5, lane = t & 31;
    const int nbb = blockIdx.x * 128, mb = blockIdx.y * 128;
    const int wm = (w >> 1) * 32, wn = (w & 1) * 64;
    const int Kd = IND, nchunk = IND / 32;

    for (int it = t; it < 512; it += 256) {
        int row = it >> 2, c = it & 3;
        cpa16(smb + AH0 + row*GAP + c*16, Ahi + (size_t)(mb + row)*Kd + c*8);
        cpa16(smb + AL0 + row*GAP + c*16, Alo + (size_t)(mb + row)*Kd + c*8);
    }
    for (int it = t; it < 512; it += 256) {
        int row = it >> 4, c = it & 15;
        cpa16(smb + WH0 + row*GBP + c*16, Whi + (size_t)row*OUTD + nbb + c*8);
        cpa16(smb + WL0 + row*GBP + c*16, Wlo + (size_t)row*OUTD + nbb + c*8);
    }
    cp_commit();

    float acc[2][8][4];
#pragma unroll
    for (int mt = 0; mt < 2; mt++)
#pragma unroll
        for (int nt = 0; nt < 8; nt++)
#pragma unroll
            for (int v = 0; v < 4; v++) acc[mt][nt][v] = 0.f;

    for (int i = 0; i < nchunk; i++) {
        cp_wait0();
        __syncthreads();
        if (i + 1 < nchunk) {
            uint32_t ah = ((i + 1) & 1) ? AH1 : AH0, al = ((i + 1) & 1) ? AL1 : AL0;
            uint32_t wh = ((i + 1) & 1) ? WH1 : WH0, wl = ((i + 1) & 1) ? WL1 : WL0;
            int kc = (i + 1) * 32;
            for (int it = t; it < 512; it += 256) {
                int row = it >> 2, c = it & 3;
                cpa16(smb + ah + row*GAP + c*16, Ahi + (size_t)(mb + row)*Kd + kc + c*8);
                cpa16(smb + al + row*GAP + c*16, Alo + (size_t)(mb + row)*Kd + kc + c*8);
            }
            for (int it = t; it < 512; it += 256) {
                int row = it >> 4, c = it & 15;
                cpa16(smb + wh + row*GBP + c*16, Whi + (size_t)(kc + row)*OUTD + nbb + c*8);
                cpa16(smb + wl + row*GBP + c*16, Wlo + (size_t)(kc + row)*OUTD + nbb + c*8);
            }
            cp_commit();
        }
        const uint32_t ah = smb + ((i & 1) ? AH1 : AH0), al = smb + ((i & 1) ? AL1 : AL0);
        const uint32_t wh = smb + ((i & 1) ? WH1 : WH0), wl = smb + ((i & 1) ? WL1 : WL0);
#pragma unroll
        for (int ks = 0; ks < 2; ks++) {
            uint32_t afh[2][4], afl[2][4];
#pragma unroll
            for (int mt = 0; mt < 2; mt++) {
                uint32_t aoff = (wm + mt*16 + (lane & 15))*GAP + ks*32 + (lane >> 4)*16;
                ldsm4(afh[mt], ah + aoff);
                ldsm4(afl[mt], al + aoff);
            }
#pragma unroll
            for (int nt = 0; nt < 8; nt++) {
                uint32_t boff = (ks*16 + (lane & 15))*GBP + (wn + nt*8)*2;
                uint32_t bfh[2], bfl[2];
                ldsm2t(bfh, wh + boff);
                ldsm2t(bfl, wl + boff);
#pragma unroll
                for (int mt = 0; mt < 2; mt++) {
                    mma16816(acc[mt][nt], afh[mt], bfh);
                    mma16816(acc[mt][nt], afh[mt], bfl);
                    mma16816(acc[mt][nt], afl[mt], bfh);
                }
            }
        }
    }
#pragma unroll
    for (int mt = 0; mt < 2; mt++) {
#pragma unroll
        for (int nt = 0; nt < 8; nt++) {
            int m0 = mb + wm + mt*16 + (lane >> 2);
            int n0 = nbb + wn + nt*8 + 2*(lane & 3);
            float b0 = bias[n0], b1v = bias[n0 + 1];
#pragma unroll
            for (int rr = 0; rr < 2; rr++) {
                int m = m0 + rr * 8;
                float v0 = fmaxf(acc[mt][nt][rr*2 + 0] + b0, 0.f);
                float v1 = fmaxf(acc[mt][nt][rr*2 + 1] + b1v, 0.f);
                __half h0 = __float2half_rn(v0), h1 = __float2half_rn(v1);
                __half l0 = __float2half_rn(v0 - __half2float(h0));
                __half l1 = __float2half_rn(v1 - __half2float(h1));
                uint2 pk;
                pk.x = (uint32_t)__half_as_ushort(h0) | ((uint32_t)__half_as_ushort(l0) << 16);
                pk.y = (uint32_t)__half_as_ushort(h1) | ((uint32_t)__half_as_ushort(l1) << 16);
                *(uint2*)(Cp + (size_t)m * OUTD + n0) = pk;
            }
        }
    }
}

// ---------------- GEMM2: out = ah@W2 + x@Ws + (b2+bs) -----------------------
__global__ __launch_bounds__(256)
void k_gemm2(const __half* __restrict__ A1h, const __half* __restrict__ A1l,
             const __half* __restrict__ W1h_, const __half* __restrict__ W1l_,
             const __half* __restrict__ A2h, const __half* __restrict__ A2l,
             const __half* __restrict__ W2h_, const __half* __restrict__ W2l_,
             const float* __restrict__ bias1, const float* __restrict__ bias2,
             float* __restrict__ C) {
    extern __shared__ char sm[];
    const uint32_t smb = smem_u32(sm);
    const int t = threadIdx.x, w = t >> 5, lane = t & 31;
    const int nbb = blockIdx.x * 128, mb = blockIdx.y * 128;
    const int wm = (w >> 1) * 32, wn = (w & 1) * 64;
    const int NC1 = OUTD / 32;
    const int NC = NC1 + IND / 32;

    auto prefetch = [&](int j, int pb) {
        uint32_t ah = pb ? AH1 : AH0, al = pb ? AL1 : AL0;
        uint32_t wh = pb ? WH1 : WH0, wl = pb ? WL1 : WL0;
        const __half *Ah, *Al, *Wh, *Wl;
        int Kd, kc;
        if (j < NC1) { Ah = A1h; Al = A1l; Wh = W1h_; Wl = W1l_; Kd = OUTD; kc = j * 32; }
        else         { Ah = A2h; Al = A2l; Wh = W2h_; Wl = W2l_; Kd = IND;  kc = (j - NC1) * 32; }
        for (int it = t; it < 512; it += 256) {
            int row = it >> 2, c = it & 3;
            cpa16(smb + ah + row*GAP + c*16, Ah + (size_t)(mb + row)*Kd + kc + c*8);
            cpa16(smb + al + row*GAP + c*16, Al + (size_t)(mb + row)*Kd + kc + c*8);
        }
        for (int it = t; it < 512; it += 256) {
            int row = it >> 4, c = it & 15;
            cpa16(smb + wh + row*GBP + c*16, Wh + (size_t)(kc + row)*OUTD + nbb + c*8);
            cpa16(smb + wl + row*GBP + c*16, Wl + (size_t)(kc + row)*OUTD + nbb + c*8);
        }
        cp_commit();
    };

    prefetch(0, 0);

    float acc[2][8][4];
#pragma unroll
    for (int mt = 0; mt < 2; mt++)
#pragma unroll
        for (int nt = 0; nt < 8; nt++)
#pragma unroll
            for (int v = 0; v < 4; v++) acc[mt][nt][v] = 0.f;

    for (int i = 0; i < NC; i++) {
        cp_wait0();
        __syncthreads();
        if (i + 1 < NC) prefetch(i + 1, (i + 1) & 1);
        const uint32_t ah = smb + ((i & 1) ? AH1 : AH0), al = smb + ((i & 1) ? AL1 : AL0);
        const uint32_t wh = smb + ((i & 1) ? WH1 : WH0), wl = smb + ((i & 1) ? WL1 : WL0);
#pragma unroll
        for (int ks = 0; ks < 2; ks++) {
            uint32_t afh[2][4], afl[2][4];
#pragma unroll
            for (int mt = 0; mt < 2; mt++) {
                uint32_t aoff = (wm + mt*16 + (lane & 15))*GAP + ks*32 + (lane >> 4)*16;
                ldsm4(afh[mt], ah + aoff);
                ldsm4(afl[mt], al + aoff);
            }
#pragma unroll
            for (int nt = 0; nt < 8; nt++) {
                uint32_t boff = (ks*16 + (lane & 15))*GBP + (wn + nt*8)*2;
                uint32_t bfh[2], bfl[2];
                ldsm2t(bfh, wh + boff);
                ldsm2t(bfl, wl + boff);
#pragma unroll
                for (int mt = 0; mt < 2; mt++) {
                    mma16816(acc[mt][nt], afh[mt], bfh);
                    mma16816(acc[mt][nt], afh[mt], bfl);
                    mma16816(acc[mt][nt], afl[mt], bfh);
                }
            }
        }
    }
#pragma unroll
    for (int mt = 0; mt < 2; mt++) {
#pragma unroll
        for (int nt = 0; nt < 8; nt++) {
            int m0 = mb + wm + mt*16 + (lane >> 2);
            int n0 = nbb + wn + nt*8 + 2*(lane & 3);
            float b0 = bias1[n0] + bias2[n0];
            float b1v = bias1[n0 + 1] + bias2[n0 + 1];
            float2 v0 = make_float2(acc[mt][nt][0] + b0, acc[mt][nt][1] + b1v);
            float2 v1 = make_float2(acc[mt][nt][2] + b0, acc[mt][nt][3] + b1v);
            *(float2*)(C + (size_t)m0 * OUTD + n0) = v0;
            *(float2*)(C + (size_t)(m0 + 8) * OUTD + n0) = v1;
        }
    }
}

// ---------------- launch ----------------
extern "C" void kernel_launch(void* const* d_in, const int* in_sizes, int n_in,
                              void* d_out, int out_size) {
    const float* x  = (const float*)d_in[0];
    const float* W1 = (const float*)d_in[2];
    const float* b1 = (const float*)d_in[3];
    const float* W2 = (const float*)d_in[4];
    const float* b2 = (const float*)d_in[5];
    const float* Ws = (const float*)d_in[6];
    const float* bs = (const float*)d_in[7];

    float* out  = (float*)d_out;
    float* esrc = out + (size_t)NTOT * OUTD;
    float* edst = esrc + NEDGE;
    int we = (out_size >= (int)((size_t)NTOT * OUTD + 2 * NEDGE)) ? 1 : 0;

    __half *xh, *xl, *axh, *axl, *ahh, *ahl;
    uint32_t *h1p;
    __half *w1h, *w1l, *w2h, *w2l, *wsh, *wsl;
    cudaGetSymbolAddress((void**)&xh, d_xh);
    cudaGetSymbolAddress((void**)&xl, d_xl);
    cudaGetSymbolAddress((void**)&axh, d_axh);
    cudaGetSymbolAddress((void**)&axl, d_axl);
    cudaGetSymbolAddress((void**)&h1p, d_h1p);
    cudaGetSymbolAddress((void**)&ahh, d_ahh);
    cudaGetSymbolAddress((void**)&ahl, d_ahl);
    cudaGetSymbolAddress((void**)&w1h, d_w1h);
    cudaGetSymbolAddress((void**)&w1l, d_w1l);
    cudaGetSymbolAddress((void**)&w2h, d_w2h);
    cudaGetSymbolAddress((void**)&w2l, d_w2l);
    cudaGetSymbolAddress((void**)&wsh, d_wsh);
    cudaGetSymbolAddress((void**)&wsl, d_wsl);

    cudaFuncSetAttribute(k_knn, cudaFuncAttributeMaxDynamicSharedMemorySize, SMTOT);
    cudaFuncSetAttribute(k_gemm1, cudaFuncAttributeMaxDynamicSharedMemorySize, GSM);
    cudaFuncSetAttribute(k_gemm2, cudaFuncAttributeMaxDynamicSharedMemorySize, GSM);

    // launch order: k_knn at index 3 (ncu captures launch #3)
    k_prep<<<NTOT / 8, 256>>>(x);                                            // 0
    k_splitw<<<(IND * OUTD + 255) / 256, 256>>>(W1, w1h, w1l, IND * OUTD);   // 1
    k_splitw<<<(IND * OUTD + 255) / 256, 256>>>(Ws, wsh, wsl, IND * OUTD);   // 2
    k_knn<<<dim3(NN / 128, NB), 256, SMTOT>>>(xh, xl, esrc, edst, we);       // 3
    k_splitw<<<(OUTD * OUTD + 255) / 256, 256>>>(W2, w2h, w2l, OUTD * OUTD); // 4
    k_aggx<<<NTOT / 2, 256>>>(x, axh, axl);                                  // 5
    k_gemm1<<<dim3(OUTD / 128, NTOT / 128), 256, GSM>>>(axh, axl, w1h, w1l, b1, h1p); // 6
    k_aggh<<<NTOT, 256>>>(h1p, ahh, ahl);                                    // 7
    k_gemm2<<<dim3(OUTD / 128, NTOT / 128), 256, GSM>>>(ahh, ahl, w2h, w2l,
                                                        xh, xl, wsh, wsl,
                                                        b2, bs, out);        // 8
}